// round 9
// baseline (speedup 1.0000x reference)
#include <cuda_runtime.h>
#include <cuda_bf16.h>
#include <math.h>
#include <string.h>
#include <stdint.h>

// ---------------------------------------------------------------------------
//  H=16, D=128, d=2048, N_BASIS=1024, l=512, QLEN=2048, RIDGE=0.5
//  GEMMs on HMMA (mma.sync m16n8k16 bf16), split-bf16 3-pass for ~fp32.
//  r[q][n] analytic; scores never materialized.
// ---------------------------------------------------------------------------

typedef __nv_bfloat16 bf16;

// ------------------------- device scratch (static) -------------------------
__device__ bf16 g_Wh [2u*2048*2048], g_Wl [2u*2048*2048];
__device__ bf16 g_kh [512*2048],     g_kl [512*2048];
__device__ bf16 g_qh [16*2048*128],  g_ql [16*2048*128];
__device__ bf16 g_Woh[2048*2048],    g_Wol[2048*2048];
__device__ bf16 g_G2h[1024*512],     g_G2l[1024*512];
__device__ bf16 g_KVth[4096*512],    g_KVtl[4096*512];
__device__ bf16 g_keysh[1024*2048],  g_keysl[1024*2048];
__device__ bf16 g_valTh[2048*1024],  g_valTl[2048*1024];
__device__ float g_part[16u*16*128*16];
__device__ float g_params[32768u*8];
__device__ bf16 g_ctxh[2048*2048],   g_ctxl[2048*2048];

// ------------------------- host-side G2 (fp64 solve) -----------------------
static double hF[1024 * 1024];
static double hA[1024 * 1024];
static double hX[1024 * 1024];
static __align__(16) bf16 hG2h[1024 * 512];
static __align__(16) bf16 hG2l[1024 * 512];
static double hbmu[1024], hbsig[1024];
static int    hlo[1024], hhi[1024];

static void compute_G2_host()
{
    const int n = 1024, P = 1024;
    for (int i = 0; i < 512; i++) {
        double m = (double)i / 511.0;
        hbmu[2*i] = m;  hbmu[2*i+1] = m;
        hbsig[2*i] = 0.005; hbsig[2*i+1] = 0.01;
    }
    const double shift = 1.0 / 1024.0;
    const double start = -0.5 + shift, stop = 1.5 - shift;
    const double step  = (stop - start) / (double)(P - 1);
    const double inv_sqrt2pi = 0.39894228040143267794;

    for (int b = 0; b < n; b++) {
        double mu = hbmu[b], sg = hbsig[b];
        double c = inv_sqrt2pi / sg;
        int lo = P, hi = 0;
        for (int p = 0; p < P; p++) {
            double x = start + p * step;
            double t = (x - mu) / sg;
            double v = (fabs(t) < 38.0) ? c * exp(-0.5 * t * t) : 0.0;
            hF[(long)b * P + p] = v;
            if (v != 0.0) { if (p < lo) lo = p; if (p + 1 > hi) hi = p + 1; }
        }
        hlo[b] = lo; hhi[b] = hi;
    }

    memset(hA, 0, sizeof(hA));
    for (int i = 0; i < n; i++) {
        for (int j = i; j < n; j++) {
            int lo = hlo[i] > hlo[j] ? hlo[i] : hlo[j];
            int hi = hhi[i] < hhi[j] ? hhi[i] : hhi[j];
            double s = 0.0;
            if (lo < hi) {
                const double* fi = &hF[(long)i * P];
                const double* fj = &hF[(long)j * P];
                for (int p = lo; p < hi; p++) s += fi[p] * fj[p];
            }
            if (i == j) s += 0.5;
            hA[(long)i * n + j] = s;
            hA[(long)j * n + i] = s;
        }
    }
    for (int i = 0; i < n; i++) {
        for (int j = 0; j <= i; j++) {
            double s = hA[(long)i * n + j];
            const double* Li = &hA[(long)i * n];
            const double* Lj = &hA[(long)j * n];
            for (int k2 = 0; k2 < j; k2++) s -= Li[k2] * Lj[k2];
            if (j == i) hA[(long)i * n + i] = sqrt(s);
            else        hA[(long)i * n + j] = s / hA[(long)j * n + j];
        }
    }
    memcpy(hX, hF, sizeof(hX));
    for (int i = 0; i < n; i++) {
        double* xi = &hX[(long)i * P];
        const double* Li = &hA[(long)i * n];
        for (int k2 = 0; k2 < i; k2++) {
            double l = Li[k2];
            if (l != 0.0) {
                const double* xk = &hX[(long)k2 * P];
                for (int p = 0; p < P; p++) xi[p] -= l * xk[p];
            }
        }
        double inv = 1.0 / hA[(long)i * n + i];
        for (int p = 0; p < P; p++) xi[p] *= inv;
    }
    for (int i = n - 1; i >= 0; i--) {
        double* xi = &hX[(long)i * P];
        for (int k2 = i + 1; k2 < n; k2++) {
            double l = hA[(long)k2 * n + i];
            if (l != 0.0) {
                const double* xk = &hX[(long)k2 * P];
                for (int p = 0; p < P; p++) xi[p] -= l * xk[p];
            }
        }
        double inv = 1.0 / hA[(long)i * n + i];
        for (int p = 0; p < P; p++) xi[p] *= inv;
    }
    for (int b = 0; b < n; b++)
        for (int l = 0; l < 512; l++) {
            float v = (float)hX[(long)b * P + 256 + l];
            bf16 h = __float2bfloat16(v);
            hG2h[b * 512 + l] = h;
            hG2l[b * 512 + l] = __float2bfloat16(v - __bfloat162float(h));
        }
}

// ------------------------- PTX helpers -------------------------------------
__device__ __forceinline__ uint32_t smem_u32(const void* p) {
    uint32_t a;
    asm("{ .reg .u64 t; cvta.to.shared.u64 t, %1; cvt.u32.u64 %0, t; }" : "=r"(a) : "l"(p));
    return a;
}
__device__ __forceinline__ void ldsm4(uint32_t* r, uint32_t addr) {
    asm volatile("ldmatrix.sync.aligned.m8n8.x4.shared.b16 {%0,%1,%2,%3}, [%4];"
                 : "=r"(r[0]), "=r"(r[1]), "=r"(r[2]), "=r"(r[3]) : "r"(addr));
}
__device__ __forceinline__ void mma16816(float* d,
                                         uint32_t a0, uint32_t a1, uint32_t a2, uint32_t a3,
                                         uint32_t b0, uint32_t b1) {
    asm volatile("mma.sync.aligned.m16n8k16.row.col.f32.bf16.bf16.f32 "
                 "{%0,%1,%2,%3}, {%4,%5,%6,%7}, {%8,%9}, {%0,%1,%2,%3};"
                 : "+f"(d[0]), "+f"(d[1]), "+f"(d[2]), "+f"(d[3])
                 : "r"(a0), "r"(a1), "r"(a2), "r"(a3), "r"(b0), "r"(b1));
}
#define CP_ASYNC16(dst, src) \
    asm volatile("cp.async.cg.shared.global [%0], [%1], 16;" :: "r"(dst), "l"(src) : "memory")
#define CP_COMMIT() asm volatile("cp.async.commit_group;" ::: "memory")
#define CP_WAIT_1()  asm volatile("cp.async.wait_group 1;" ::: "memory")
#define CP_WAIT_0()  asm volatile("cp.async.wait_group 0;" ::: "memory")

// ------------------------- small kernels -----------------------------------
__global__ void split_kernel(const float4* __restrict__ src,
                             uint2* __restrict__ dhi, uint2* __restrict__ dlo, int n4)
{
    int i = blockIdx.x * blockDim.x + threadIdx.x;
    if (i >= n4) return;
    float4 v = src[i];
    bf16 h0 = __float2bfloat16(v.x), h1 = __float2bfloat16(v.y);
    bf16 h2 = __float2bfloat16(v.z), h3 = __float2bfloat16(v.w);
    __nv_bfloat162 ha = {h0, h1}, hb = {h2, h3};
    __nv_bfloat162 la = {__float2bfloat16(v.x - __bfloat162float(h0)),
                         __float2bfloat16(v.y - __bfloat162float(h1))};
    __nv_bfloat162 lb = {__float2bfloat16(v.z - __bfloat162float(h2)),
                         __float2bfloat16(v.w - __bfloat162float(h3))};
    uint2 hh, ll;
    hh.x = *(uint32_t*)&ha; hh.y = *(uint32_t*)&hb;
    ll.x = *(uint32_t*)&la; ll.y = *(uint32_t*)&lb;
    dhi[i] = hh; dlo[i] = ll;
}

__global__ void copy_g2_kernel(const uint4* __restrict__ sh, const uint4* __restrict__ sl,
                               uint4* __restrict__ dh, uint4* __restrict__ dl, int n16)
{
    int i = blockIdx.x * blockDim.x + threadIdx.x;
    if (i < n16) { dh[i] = sh[i]; dl[i] = sl[i]; }
}

__global__ void reduce_params(const float* __restrict__ gpart, float* __restrict__ params)
{
    int row = blockIdx.x * 256 + threadIdx.x;
    float m = 0.f, g = 0.f;
    #pragma unroll
    for (int b = 0; b < 8; b++) {
        m += gpart[row * 16 + b * 2 + 0];
        g += gpart[row * 16 + b * 2 + 1];
    }
    float mu  = 1.f / (1.f + __expf(-m));
    float sp  = (g > 20.f) ? g : log1pf(__expf(g));
    float var = fmaxf(sp, 1e-4f);
    float sv0 = var + 2.5e-5f;
    float sv1 = var + 1.0e-4f;
    params[row * 8 + 0] = mu;
    params[row * 8 + 1] = rsqrtf(6.28318530717958648f * sv0);
    params[row * 8 + 2] = -0.5f / sv0;
    params[row * 8 + 3] = rsqrtf(6.28318530717958648f * sv1);
    params[row * 8 + 4] = -0.5f / sv1;
}

// ------------------------- HMMA split GEMM body ----------------------------
static const int ROWB   = 80;
static const int TILE_B = 128 * ROWB;
static const int OFF_AH = 0, OFF_AL = TILE_B, OFF_BH = 2*TILE_B, OFF_BL = 3*TILE_B;
static const int STAGE_B = 4 * TILE_B;        // 40960
static const int SMEM_BYTES = 2 * STAGE_B;    // 81920

template<int OUT_MODE>
__device__ __forceinline__
void mma_body(char* dsm, int bx, int by, int bz,
              const bf16* __restrict__ Ah, const bf16* __restrict__ Al, int lda, long long sA,
              const bf16* __restrict__ Bh, const bf16* __restrict__ Bl, int ldb, long long sB,
              float* __restrict__ C, bf16* __restrict__ Ch, bf16* __restrict__ Cl,
              int ldc, long long sC, int K, float alpha,
              const float* __restrict__ wmu, const float* __restrict__ wsg,
              float* __restrict__ gpart)
{
    const uint32_t sb = smem_u32(dsm);
    const int tid = threadIdx.x, lane = tid & 31, wid = tid >> 5;
    const int warp_m = wid >> 2, warp_n = wid & 3;

    const bf16* A0h = Ah + (long long)bz * sA + (long long)(by * 128) * lda;
    const bf16* A0l = Al + (long long)bz * sA + (long long)(by * 128) * lda;
    const bf16* B0h = Bh + (long long)bz * sB + (long long)(bx * 128) * ldb;
    const bf16* B0l = Bl + (long long)bz * sB + (long long)(bx * 128) * ldb;

    const int c0 = tid, c1 = tid + 256;
    const int r0 = c0 >> 2, q0 = c0 & 3;
    const int r1 = c1 >> 2, q1 = c1 & 3;

    auto load_stage = [&](int s, int k0) {
        uint32_t d = sb + s * STAGE_B;
        uint32_t d0 = (uint32_t)(r0 * ROWB + q0 * 16);
        uint32_t d1 = (uint32_t)(r1 * ROWB + q1 * 16);
        long long gA0 = (long long)r0 * lda + k0 + q0 * 8;
        long long gA1 = (long long)r1 * lda + k0 + q1 * 8;
        long long gB0 = (long long)r0 * ldb + k0 + q0 * 8;
        long long gB1 = (long long)r1 * ldb + k0 + q1 * 8;
        CP_ASYNC16(d + OFF_AH + d0, A0h + gA0);
        CP_ASYNC16(d + OFF_AH + d1, A0h + gA1);
        CP_ASYNC16(d + OFF_AL + d0, A0l + gA0);
        CP_ASYNC16(d + OFF_AL + d1, A0l + gA1);
        CP_ASYNC16(d + OFF_BH + d0, B0h + gB0);
        CP_ASYNC16(d + OFF_BH + d1, B0h + gB1);
        CP_ASYNC16(d + OFF_BL + d0, B0l + gB0);
        CP_ASYNC16(d + OFF_BL + d1, B0l + gB1);
    };

    const int lr = lane & 15;
    const uint32_t lc = (uint32_t)((lane >> 4) * 16);
    uint32_t aoff[4], boff[2];
    #pragma unroll
    for (int mt = 0; mt < 4; mt++)
        aoff[mt] = (uint32_t)((warp_m * 64 + mt * 16 + lr) * ROWB) + lc;
    #pragma unroll
    for (int n2 = 0; n2 < 2; n2++)
        boff[n2] = (uint32_t)((warp_n * 32 + n2 * 16 + lr) * ROWB) + lc;

    float acc[4][4][4];
    #pragma unroll
    for (int i = 0; i < 4; i++)
        #pragma unroll
        for (int j = 0; j < 4; j++)
            #pragma unroll
            for (int v = 0; v < 4; v++) acc[i][j][v] = 0.f;

    const int nk = K >> 5;
    load_stage(0, 0);
    CP_COMMIT();

    for (int t = 0; t < nk; t++) {
        if (t + 1 < nk) { load_stage((t + 1) & 1, (t + 1) << 5); CP_COMMIT(); CP_WAIT_1(); }
        else            { CP_WAIT_0(); }
        __syncthreads();

        const uint32_t s = sb + (t & 1) * STAGE_B;
        #pragma unroll
        for (int k16 = 0; k16 < 2; k16++) {
            const uint32_t kb = (uint32_t)(k16 * 32);
            uint32_t ah[4][4], al[4][4], bh[2][4], bl[2][4];
            #pragma unroll
            for (int mt = 0; mt < 4; mt++) ldsm4(ah[mt], s + OFF_AH + aoff[mt] + kb);
            #pragma unroll
            for (int n2 = 0; n2 < 2; n2++) ldsm4(bh[n2], s + OFF_BH + boff[n2] + kb);
            #pragma unroll
            for (int mt = 0; mt < 4; mt++)
                #pragma unroll
                for (int nt = 0; nt < 4; nt++) {
                    const uint32_t* b = bh[nt >> 1];
                    mma16816(acc[mt][nt], ah[mt][0], ah[mt][1], ah[mt][2], ah[mt][3],
                             (nt & 1) ? b[1] : b[0], (nt & 1) ? b[3] : b[2]);
                }
            #pragma unroll
            for (int n2 = 0; n2 < 2; n2++) ldsm4(bl[n2], s + OFF_BL + boff[n2] + kb);
            #pragma unroll
            for (int mt = 0; mt < 4; mt++)
                #pragma unroll
                for (int nt = 0; nt < 4; nt++) {
                    const uint32_t* b = bl[nt >> 1];
                    mma16816(acc[mt][nt], ah[mt][0], ah[mt][1], ah[mt][2], ah[mt][3],
                             (nt & 1) ? b[1] : b[0], (nt & 1) ? b[3] : b[2]);
                }
            #pragma unroll
            for (int mt = 0; mt < 4; mt++) ldsm4(al[mt], s + OFF_AL + aoff[mt] + kb);
            #pragma unroll
            for (int mt = 0; mt < 4; mt++)
                #pragma unroll
                for (int nt = 0; nt < 4; nt++) {
                    const uint32_t* b = bh[nt >> 1];
                    mma16816(acc[mt][nt], al[mt][0], al[mt][1], al[mt][2], al[mt][3],
                             (nt & 1) ? b[1] : b[0], (nt & 1) ? b[3] : b[2]);
                }
        }
        __syncthreads();
    }

    const int group = lane >> 2, tig = lane & 3;
    if (OUT_MODE == 2) {
        float pmu[8], psg[8];
        #pragma unroll
        for (int i = 0; i < 8; i++) { pmu[i] = 0.f; psg[i] = 0.f; }
        #pragma unroll
        for (int mt = 0; mt < 4; mt++)
            #pragma unroll
            for (int nt = 0; nt < 4; nt++) {
                int c = bx * 128 + warp_n * 32 + nt * 8 + tig * 2;
                float w0m = wmu[c], w1m = wmu[c + 1];
                float w0s = wsg[c], w1s = wsg[c + 1];
                pmu[mt * 2 + 0] += acc[mt][nt][0] * w0m + acc[mt][nt][1] * w1m;
                pmu[mt * 2 + 1] += acc[mt][nt][2] * w0m + acc[mt][nt][3] * w1m;
                psg[mt * 2 + 0] += acc[mt][nt][0] * w0s + acc[mt][nt][1] * w1s;
                psg[mt * 2 + 1] += acc[mt][nt][2] * w0s + acc[mt][nt][3] * w1s;
            }
        #pragma unroll
        for (int o = 1; o <= 2; o <<= 1)
            #pragma unroll
            for (int i = 0; i < 8; i++) {
                pmu[i] += __shfl_xor_sync(0xffffffffu, pmu[i], o);
                psg[i] += __shfl_xor_sync(0xffffffffu, psg[i], o);
            }
        float* sp = (float*)dsm;
        __syncthreads();
        if (tig == 0) {
            #pragma unroll
            for (int mt = 0; mt < 4; mt++) {
                int ra = warp_m * 64 + mt * 16 + group;
                sp[(ra * 4 + warp_n) * 2 + 0] = pmu[mt * 2 + 0];
                sp[(ra * 4 + warp_n) * 2 + 1] = psg[mt * 2 + 0];
                sp[((ra + 8) * 4 + warp_n) * 2 + 0] = pmu[mt * 2 + 1];
                sp[((ra + 8) * 4 + warp_n) * 2 + 1] = psg[mt * 2 + 1];
            }
        }
        __syncthreads();
        if (tid < 128) {
            float m = 0.f, g = 0.f;
            #pragma unroll
            for (int w = 0; w < 4; w++) {
                m += sp[(tid * 4 + w) * 2 + 0];
                g += sp[(tid * 4 + w) * 2 + 1];
            }
            long long ridx = ((long long)(bz * 16 + by) * 128 + tid);
            gpart[ridx * 16 + bx * 2 + 0] = m * alpha;
            gpart[ridx * 16 + bx * 2 + 1] = g * alpha;
        }
        return;
    }

    #pragma unroll
    for (int mt = 0; mt < 4; mt++) {
        #pragma unroll
        for (int nt = 0; nt < 4; nt++) {
            int row = by * 128 + warp_m * 64 + mt * 16 + group;
            int col = bx * 128 + warp_n * 32 + nt * 8 + tig * 2;
            float v0 = alpha * acc[mt][nt][0], v1 = alpha * acc[mt][nt][1];
            float v2 = alpha * acc[mt][nt][2], v3 = alpha * acc[mt][nt][3];
            if (OUT_MODE == 0) {
                float* p0 = C + (long long)bz * sC + (long long)row * ldc + col;
                float* p1 = p0 + 8LL * ldc;
                *(float2*)p0 = make_float2(v0, v1);
                *(float2*)p1 = make_float2(v2, v3);
            } else {
                long long o0 = (long long)bz * sC + (long long)row * ldc + col;
                long long o1 = o0 + 8LL * ldc;
                bf16 h0 = __float2bfloat16(v0), h1 = __float2bfloat16(v1);
                bf16 h2 = __float2bfloat16(v2), h3 = __float2bfloat16(v3);
                __nv_bfloat162 hh0 = {h0, h1}, hh1 = {h2, h3};
                __nv_bfloat162 ll0 = {__float2bfloat16(v0 - __bfloat162float(h0)),
                                      __float2bfloat16(v1 - __bfloat162float(h1))};
                __nv_bfloat162 ll1 = {__float2bfloat16(v2 - __bfloat162float(h2)),
                                      __float2bfloat16(v3 - __bfloat162float(h3))};
                *(__nv_bfloat162*)(Ch + o0) = hh0;
                *(__nv_bfloat162*)(Cl + o0) = ll0;
                *(__nv_bfloat162*)(Ch + o1) = hh1;
                *(__nv_bfloat162*)(Cl + o1) = ll1;
            }
        }
    }
}

template<int OUT_MODE>
__global__ __launch_bounds__(256, 2)
void mma_gemm(const bf16* __restrict__ Ah, const bf16* __restrict__ Al, int lda, long long sA,
              const bf16* __restrict__ Bh, const bf16* __restrict__ Bl, int ldb, long long sB,
              float* __restrict__ C, bf16* __restrict__ Ch, bf16* __restrict__ Cl,
              int ldc, long long sC, int K, float alpha,
              const float* __restrict__ wmu, const float* __restrict__ wsg,
              float* __restrict__ gpart)
{
    extern __shared__ char dsm[];
    mma_body<OUT_MODE>(dsm, blockIdx.x, blockIdx.y, blockIdx.z,
                       Ah, Al, lda, sA, Bh, Bl, ldb, sB,
                       C, Ch, Cl, ldc, sC, K, alpha, wmu, wsg, gpart);
}

// Fused GEMM2a + GEMM2b (independent; one 256-CTA launch fills the chip)
__global__ __launch_bounds__(256, 2)
void gemm2_fused(const bf16* __restrict__ G2h, const bf16* __restrict__ G2l,
                 const bf16* __restrict__ KVth, const bf16* __restrict__ KVtl,
                 bf16* __restrict__ keysh, bf16* __restrict__ keysl,
                 bf16* __restrict__ valTh, bf16* __restrict__ valTl)
{
    extern __shared__ char dsm[];
    int id = blockIdx.x;
    if (id < 128) {
        // 2a: keys[n][j] = G2[n]·KVt_key[j]   M=1024 N=2048 K=512, grid (16, 8)
        mma_body<1>(dsm, id & 15, id >> 4, 0,
                    G2h, G2l, 512, 0, KVth, KVtl, 512, 0,
                    nullptr, keysh, keysl, 2048, 0,
                    512, 1.0f, nullptr, nullptr, nullptr);
    } else {
        // 2b: valT[j][n] = KVt_val[j]·G2[n]   M=2048 N=1024 K=512, grid (8, 16)
        int j = id - 128;
        mma_body<1>(dsm, j & 7, j >> 3, 0,
                    KVth + 2048LL * 512, KVtl + 2048LL * 512, 512, 0,
                    G2h, G2l, 512, 0,
                    nullptr, valTh, valTl, 1024, 0,
                    512, 1.0f, nullptr, nullptr, nullptr);
    }
}

// ------------------------- analytic-A GEMM (ctx = r · valT^T) --------------
static const int R_SMEM = 2 * (2 * TILE_B);   // 40960

__global__ __launch_bounds__(256, 1)
void gemm_r(const bf16* __restrict__ Bh, const bf16* __restrict__ Bl,
            const float* __restrict__ params,
            bf16* __restrict__ Ch, bf16* __restrict__ Cl)
{
    extern __shared__ char dsm[];
    const uint32_t sb = smem_u32(dsm);
    const int tid = threadIdx.x, lane = tid & 31, wid = tid >> 5;
    const int warp_m = wid >> 2, warp_n = wid & 3;
    const int by = blockIdx.y, bz = blockIdx.z;
    const int group = lane >> 2, tig = lane & 3;
    const float INV511 = 1.0f / 511.0f;

    const bf16* B0h = Bh + (long long)(bz * 128) * 1024;
    const bf16* B0l = Bl + (long long)(bz * 128) * 1024;

    float mu_[8], c0_[8], h0_[8], c1_[8], h1_[8];
    {
        const long long pbase = (long long)(bz * 2048 + by * 128);
        #pragma unroll
        for (int mt = 0; mt < 4; mt++) {
            int ra = warp_m * 64 + mt * 16 + group;
            const float* p0 = params + (pbase + ra) * 8;
            const float* p1 = params + (pbase + ra + 8) * 8;
            mu_[mt*2+0] = p0[0]; c0_[mt*2+0] = p0[1]; h0_[mt*2+0] = p0[2];
            c1_[mt*2+0] = p0[3]; h1_[mt*2+0] = p0[4];
            mu_[mt*2+1] = p1[0]; c0_[mt*2+1] = p1[1]; h0_[mt*2+1] = p1[2];
            c1_[mt*2+1] = p1[3]; h1_[mt*2+1] = p1[4];
        }
    }

    auto load_stage = [&](int s, int k0) {
        uint32_t d = sb + s * (2 * TILE_B);
        #pragma unroll
        for (int j = 0; j < 4; j++) {
            int c = tid + j * 256;
            int plane = c >> 9, idx = c & 511;
            int row = idx >> 2, q4 = idx & 3;
            uint32_t dst = d + plane * TILE_B + (uint32_t)(row * ROWB + q4 * 16);
            const bf16* src = (plane ? B0l : B0h) + (long long)row * 1024 + k0 + q4 * 8;
            CP_ASYNC16(dst, src);
        }
    };

    const int lr = lane & 15;
    const uint32_t lc = (uint32_t)((lane >> 4) * 16);
    uint32_t boff[2];
    #pragma unroll
    for (int n2 = 0; n2 < 2; n2++)
        boff[n2] = (uint32_t)((warp_n * 32 + n2 * 16 + lr) * ROWB) + lc;

    float acc[4][4][4];
    #pragma unroll
    for (int i = 0; i < 4; i++)
        #pragma unroll
        for (int j = 0; j < 4; j++)
            #pragma unroll
            for (int v = 0; v < 4; v++) acc[i][j][v] = 0.f;

    load_stage(0, 0);
    CP_COMMIT();

    for (int t = 0; t < 32; t++) {
        if (t + 1 < 32) { load_stage((t + 1) & 1, (t + 1) << 5); CP_COMMIT(); CP_WAIT_1(); }
        else            { CP_WAIT_0(); }
        __syncthreads();

        const uint32_t s = sb + (t & 1) * (2 * TILE_B);
        #pragma unroll
        for (int k16 = 0; k16 < 2; k16++) {
            const int kb = t * 32 + k16 * 16;
            const uint32_t kbb = (uint32_t)(k16 * 32);
            uint32_t bh[2][4], bl[2][4];
            #pragma unroll
            for (int n2 = 0; n2 < 2; n2++) {
                ldsm4(bh[n2], s + boff[n2] + kbb);
                ldsm4(bl[n2], s + TILE_B + boff[n2] + kbb);
            }
            const float bmu0 = (float)((kb >> 1) + tig) * INV511;
            const float bmu1 = bmu0 + 4.0f * INV511;
            #pragma unroll
            for (int mt = 0; mt < 4; mt++) {
                uint32_t ah[4], al[4];
                #pragma unroll
                for (int f = 0; f < 4; f++) {
                    const int i = mt * 2 + (f & 1);
                    const float bm = (f < 2) ? bmu0 : bmu1;
                    float d = bm - mu_[i];
                    float t2 = d * d;
                    float ve = c0_[i] * __expf(h0_[i] * t2);
                    float vo = c1_[i] * __expf(h1_[i] * t2);
                    bf16 he = __float2bfloat16(ve), ho = __float2bfloat16(vo);
                    __nv_bfloat162 hh = {he, ho};
                    __nv_bfloat162 ll = {__float2bfloat16(ve - __bfloat162float(he)),
                                         __float2bfloat16(vo - __bfloat162float(ho))};
                    ah[f] = *(uint32_t*)&hh;
                    al[f] = *(uint32_t*)&ll;
                }
                #pragma unroll
                for (int nt = 0; nt < 4; nt++) {
                    const uint32_t* b = bh[nt >> 1];
                    uint32_t b0 = (nt & 1) ? b[1] : b[0], b1 = (nt & 1) ? b[3] : b[2];
                    mma16816(acc[mt][nt], ah[0], ah[1], ah[2], ah[3], b0, b1);
                    const uint32_t* bb = bl[nt >> 1];
                    uint32_t c0b = (nt & 1) ? bb[1] : bb[0], c1b = (nt & 1) ? bb[3] : bb[2];
                    mma16816(acc[mt][nt], ah[0], ah[1], ah[2], ah[3], c0b, c1b);
                    mma16816(acc[mt][nt], al[0], al[1], al[2], al[3], b0, b1);
                }
            }
        }
        __syncthreads();
    }

    #pragma unroll
    for (int mt = 0; mt < 4; mt++) {
        #pragma unroll
        for (int nt = 0; nt < 4; nt++) {
            int row = by * 128 + warp_m * 64 + mt * 16 + group;
            int col = bz * 128 + warp_n * 32 + nt * 8 + tig * 2;
            long long o0 = (long long)row * 2048 + col;
            long long o1 = o0 + 8LL * 2048;
            float v0 = acc[mt][nt][0], v1 = acc[mt][nt][1];
            float v2 = acc[mt][nt][2], v3 = acc[mt][nt][3];
            bf16 h0 = __float2bfloat16(v0), h1 = __float2bfloat16(v1);
            bf16 h2 = __float2bfloat16(v2), h3 = __float2bfloat16(v3);
            __nv_bfloat162 hh0 = {h0, h1}, hh1 = {h2, h3};
            __nv_bfloat162 ll0 = {__float2bfloat16(v0 - __bfloat162float(h0)),
                                  __float2bfloat16(v1 - __bfloat162float(h1))};
            __nv_bfloat162 ll1 = {__float2bfloat16(v2 - __bfloat162float(h2)),
                                  __float2bfloat16(v3 - __bfloat162float(h3))};
            *(__nv_bfloat162*)(Ch + o0) = hh0;
            *(__nv_bfloat162*)(Cl + o0) = ll0;
            *(__nv_bfloat162*)(Ch + o1) = hh1;
            *(__nv_bfloat162*)(Cl + o1) = ll1;
        }
    }
}

// ------------------------- launch ------------------------------------------
extern "C" void kernel_launch(void* const* d_in, const int* in_sizes, int n_in,
                              void* d_out, int out_size)
{
    (void)in_sizes; (void)n_in; (void)out_size;
    const float* dk   = (const float*)d_in[0];
    const float* dq   = (const float*)d_in[1];
    const float* dWk  = (const float*)d_in[2];
    const float* dWv  = (const float*)d_in[3];
    const float* dWo  = (const float*)d_in[4];
    const float* dwmu = (const float*)d_in[5];
    const float* dwsg = (const float*)d_in[6];
    float* dout = (float*)d_out;

    compute_G2_host();

    bf16 *pWh, *pWl, *pkh, *pkl, *pqh, *pql, *pWoh, *pWol, *pG2h, *pG2l;
    bf16 *pKVth, *pKVtl, *pkeysh, *pkeysl, *pvalTh, *pvalTl;
    bf16 *pctxh, *pctxl;
    float *ppart, *pparams;
    cudaGetSymbolAddress((void**)&pWh,   g_Wh);   cudaGetSymbolAddress((void**)&pWl,   g_Wl);
    cudaGetSymbolAddress((void**)&pkh,   g_kh);   cudaGetSymbolAddress((void**)&pkl,   g_kl);
    cudaGetSymbolAddress((void**)&pqh,   g_qh);   cudaGetSymbolAddress((void**)&pql,   g_ql);
    cudaGetSymbolAddress((void**)&pWoh,  g_Woh);  cudaGetSymbolAddress((void**)&pWol,  g_Wol);
    cudaGetSymbolAddress((void**)&pG2h,  g_G2h);  cudaGetSymbolAddress((void**)&pG2l,  g_G2l);
    cudaGetSymbolAddress((void**)&pKVth, g_KVth); cudaGetSymbolAddress((void**)&pKVtl, g_KVtl);
    cudaGetSymbolAddress((void**)&pkeysh,g_keysh);cudaGetSymbolAddress((void**)&pkeysl,g_keysl);
    cudaGetSymbolAddress((void**)&pvalTh,g_valTh);cudaGetSymbolAddress((void**)&pvalTl,g_valTl);
    cudaGetSymbolAddress((void**)&pctxh, g_ctxh); cudaGetSymbolAddress((void**)&pctxl, g_ctxl);
    cudaGetSymbolAddress((void**)&ppart, g_part); cudaGetSymbolAddress((void**)&pparams, g_params);

    cudaFuncSetAttribute(mma_gemm<0>, cudaFuncAttributeMaxDynamicSharedMemorySize, SMEM_BYTES);
    cudaFuncSetAttribute(mma_gemm<1>, cudaFuncAttributeMaxDynamicSharedMemorySize, SMEM_BYTES);
    cudaFuncSetAttribute(mma_gemm<2>, cudaFuncAttributeMaxDynamicSharedMemorySize, SMEM_BYTES);
    cudaFuncSetAttribute(gemm2_fused, cudaFuncAttributeMaxDynamicSharedMemorySize, SMEM_BYTES);
    cudaFuncSetAttribute(gemm_r,      cudaFuncAttributeMaxDynamicSharedMemorySize, R_SMEM);

    // setup launches ordered so launch index 5 (ncu -s 5 -c 1) is GEMM1
    {
        int n4 = 2048 * 2048 / 4;
        split_kernel<<<(n4 + 255) / 256, 256>>>((const float4*)dWk, (uint2*)pWh, (uint2*)pWl, n4);   // 0
        split_kernel<<<(n4 + 255) / 256, 256>>>((const float4*)dWv,
                                                (uint2*)(pWh + 2048 * 2048), (uint2*)(pWl + 2048 * 2048), n4); // 1
        int nk4 = 512 * 2048 / 4;
        split_kernel<<<(nk4 + 255) / 256, 256>>>((const float4*)dk, (uint2*)pkh, (uint2*)pkl, nk4);  // 2
        int n16 = 1024 * 512 * 2 / 16;
        copy_g2_kernel<<<(n16 + 255) / 256, 256>>>((const uint4*)hG2h, (const uint4*)hG2l,
                                                   (uint4*)pG2h, (uint4*)pG2l, n16);                 // 3
        int nq4 = 16 * 2048 * 128 / 4;
        split_kernel<<<(nq4 + 255) / 256, 256>>>((const float4*)dq, (uint2*)pqh, (uint2*)pql, nq4);  // 4
    }

    // 1: KVt[z*2048+j][l] = W[z][j]·k[l]   (launch idx 5 — ncu capture target)
    {
        dim3 g(4, 16, 2);
        mma_gemm<1><<<g, 256, SMEM_BYTES>>>(pWh, pWl, 2048, 2048LL * 2048,
                                            pkh, pkl, 2048, 0,
                                            nullptr, pKVth, pKVtl, 512, 2048LL * 512,
                                            2048, 1.0f, nullptr, nullptr, nullptr);
    }
    // Wo split (needed only before GEMM6)
    {
        int n4 = 2048 * 2048 / 4;
        split_kernel<<<(n4 + 255) / 256, 256>>>((const float4*)dWo, (uint2*)pWoh, (uint2*)pWol, n4);
    }
    // 2: fused keys + valT (256 CTAs)
    gemm2_fused<<<256, 256, SMEM_BYTES>>>(pG2h, pG2l, pKVth, pKVtl,
                                          pkeysh, pkeysl, pvalTh, pvalTl);
    // 3: scores reduced in-register -> per-row partials
    {
        dim3 g(8, 16, 16);
        mma_gemm<2><<<g, 256, SMEM_BYTES>>>(pqh, pql, 128, 2048LL * 128,
                                            pkeysh, pkeysl, 2048, 128,
                                            nullptr, nullptr, nullptr, 0, 0,
                                            128, 0.08838834764831845f, dwmu, dwsg, ppart);
    }
    // 4: fold partials -> row params
    reduce_params<<<128, 256>>>(ppart, pparams);

    // 5: ctx = r · valT^T with analytic A
    {
        dim3 g(1, 16, 16);
        gemm_r<<<g, 256, R_SMEM>>>(pvalTh, pvalTl, pparams, pctxh, pctxl);
    }
    // 6: out[q][o] = ctx[q]·Wo[o]
    {
        dim3 g(16, 16, 1);
        mma_gemm<0><<<g, 256, SMEM_BYTES>>>(pctxh, pctxl, 2048, 0,
                                            pWoh, pWol, 2048, 0,
                                            dout, nullptr, nullptr, 2048, 0,
                                            2048, 1.0f, nullptr, nullptr, nullptr);
    }
}

// round 12
// speedup vs baseline: 1.7012x; 1.7012x over previous
#include <cuda_runtime.h>
#include <cuda_bf16.h>
#include <math.h>
#include <string.h>
#include <stdint.h>

// ---------------------------------------------------------------------------
//  H=16, D=128, d=2048, N_BASIS=1024, l=512, QLEN=2048, RIDGE=0.5
//  GEMMs on HMMA (mma.sync m16n8k16 bf16), split-bf16 3-pass for ~fp32.
//  512-thread CTAs (16 warps, 4x4 grid, warp tile 32x32) for latency hiding.
// ---------------------------------------------------------------------------

typedef __nv_bfloat16 bf16;

// ------------------------- device scratch (static) -------------------------
__device__ bf16 g_Wh [2u*2048*2048], g_Wl [2u*2048*2048];
__device__ bf16 g_kh [512*2048],     g_kl [512*2048];
__device__ bf16 g_qh [16*2048*128],  g_ql [16*2048*128];
__device__ bf16 g_Woh[2048*2048],    g_Wol[2048*2048];
__device__ bf16 g_G2h[1024*512],     g_G2l[1024*512];
__device__ bf16 g_KVth[4096*512],    g_KVtl[4096*512];
__device__ bf16 g_keysh[1024*2048],  g_keysl[1024*2048];
__device__ bf16 g_valTh[2048*1024],  g_valTl[2048*1024];
__device__ float g_part[16u*16*128*16];
__device__ float g_params[32768u*8];
__device__ bf16 g_ctxh[2048*2048],   g_ctxl[2048*2048];

// ------------------------- host-side G2 (fp64 solve) -----------------------
static double hF[1024 * 1024];
static double hA[1024 * 1024];
static double hX[1024 * 1024];
static __align__(16) bf16 hG2h[1024 * 512];
static __align__(16) bf16 hG2l[1024 * 512];
static double hbmu[1024], hbsig[1024];
static int    hlo[1024], hhi[1024];

static void compute_G2_host()
{
    const int n = 1024, P = 1024;
    for (int i = 0; i < 512; i++) {
        double m = (double)i / 511.0;
        hbmu[2*i] = m;  hbmu[2*i+1] = m;
        hbsig[2*i] = 0.005; hbsig[2*i+1] = 0.01;
    }
    const double shift = 1.0 / 1024.0;
    const double start = -0.5 + shift, stop = 1.5 - shift;
    const double step  = (stop - start) / (double)(P - 1);
    const double inv_sqrt2pi = 0.39894228040143267794;

    for (int b = 0; b < n; b++) {
        double mu = hbmu[b], sg = hbsig[b];
        double c = inv_sqrt2pi / sg;
        int lo = P, hi = 0;
        for (int p = 0; p < P; p++) {
            double x = start + p * step;
            double t = (x - mu) / sg;
            double v = (fabs(t) < 38.0) ? c * exp(-0.5 * t * t) : 0.0;
            hF[(long)b * P + p] = v;
            if (v != 0.0) { if (p < lo) lo = p; if (p + 1 > hi) hi = p + 1; }
        }
        hlo[b] = lo; hhi[b] = hi;
    }

    memset(hA, 0, sizeof(hA));
    for (int i = 0; i < n; i++) {
        for (int j = i; j < n; j++) {
            int lo = hlo[i] > hlo[j] ? hlo[i] : hlo[j];
            int hi = hhi[i] < hhi[j] ? hhi[i] : hhi[j];
            double s = 0.0;
            if (lo < hi) {
                const double* fi = &hF[(long)i * P];
                const double* fj = &hF[(long)j * P];
                for (int p = lo; p < hi; p++) s += fi[p] * fj[p];
            }
            if (i == j) s += 0.5;
            hA[(long)i * n + j] = s;
            hA[(long)j * n + i] = s;
        }
    }
    for (int i = 0; i < n; i++) {
        for (int j = 0; j <= i; j++) {
            double s = hA[(long)i * n + j];
            const double* Li = &hA[(long)i * n];
            const double* Lj = &hA[(long)j * n];
            for (int k2 = 0; k2 < j; k2++) s -= Li[k2] * Lj[k2];
            if (j == i) hA[(long)i * n + i] = sqrt(s);
            else        hA[(long)i * n + j] = s / hA[(long)j * n + j];
        }
    }
    memcpy(hX, hF, sizeof(hX));
    for (int i = 0; i < n; i++) {
        double* xi = &hX[(long)i * P];
        const double* Li = &hA[(long)i * n];
        for (int k2 = 0; k2 < i; k2++) {
            double l = Li[k2];
            if (l != 0.0) {
                const double* xk = &hX[(long)k2 * P];
                for (int p = 0; p < P; p++) xi[p] -= l * xk[p];
            }
        }
        double inv = 1.0 / hA[(long)i * n + i];
        for (int p = 0; p < P; p++) xi[p] *= inv;
    }
    for (int i = n - 1; i >= 0; i--) {
        double* xi = &hX[(long)i * P];
        for (int k2 = i + 1; k2 < n; k2++) {
            double l = hA[(long)k2 * n + i];
            if (l != 0.0) {
                const double* xk = &hX[(long)k2 * P];
                for (int p = 0; p < P; p++) xi[p] -= l * xk[p];
            }
        }
        double inv = 1.0 / hA[(long)i * n + i];
        for (int p = 0; p < P; p++) xi[p] *= inv;
    }
    for (int b = 0; b < n; b++)
        for (int l = 0; l < 512; l++) {
            float v = (float)hX[(long)b * P + 256 + l];
            bf16 h = __float2bfloat16(v);
            hG2h[b * 512 + l] = h;
            hG2l[b * 512 + l] = __float2bfloat16(v - __bfloat162float(h));
        }
}

// ------------------------- PTX helpers -------------------------------------
__device__ __forceinline__ uint32_t smem_u32(const void* p) {
    uint32_t a;
    asm("{ .reg .u64 t; cvta.to.shared.u64 t, %1; cvt.u32.u64 %0, t; }" : "=r"(a) : "l"(p));
    return a;
}
__device__ __forceinline__ void ldsm4(uint32_t* r, uint32_t addr) {
    asm volatile("ldmatrix.sync.aligned.m8n8.x4.shared.b16 {%0,%1,%2,%3}, [%4];"
                 : "=r"(r[0]), "=r"(r[1]), "=r"(r[2]), "=r"(r[3]) : "r"(addr));
}
__device__ __forceinline__ void mma16816(float* d,
                                         uint32_t a0, uint32_t a1, uint32_t a2, uint32_t a3,
                                         uint32_t b0, uint32_t b1) {
    asm volatile("mma.sync.aligned.m16n8k16.row.col.f32.bf16.bf16.f32 "
                 "{%0,%1,%2,%3}, {%4,%5,%6,%7}, {%8,%9}, {%0,%1,%2,%3};"
                 : "+f"(d[0]), "+f"(d[1]), "+f"(d[2]), "+f"(d[3])
                 : "r"(a0), "r"(a1), "r"(a2), "r"(a3), "r"(b0), "r"(b1));
}
#define CP_ASYNC16(dst, src) \
    asm volatile("cp.async.cg.shared.global [%0], [%1], 16;" :: "r"(dst), "l"(src) : "memory")
#define CP_COMMIT() asm volatile("cp.async.commit_group;" ::: "memory")
#define CP_WAIT_1()  asm volatile("cp.async.wait_group 1;" ::: "memory")
#define CP_WAIT_0()  asm volatile("cp.async.wait_group 0;" ::: "memory")

__device__ __forceinline__ uint32_t pack_split_hi(float v0, float v1, uint32_t& lo) {
    bf16 h0 = __float2bfloat16(v0), h1 = __float2bfloat16(v1);
    __nv_bfloat162 hh = {h0, h1};
    __nv_bfloat162 ll = {__float2bfloat16(v0 - __bfloat162float(h0)),
                         __float2bfloat16(v1 - __bfloat162float(h1))};
    lo = *(uint32_t*)&ll;
    return *(uint32_t*)&hh;
}

// ------------------------- small kernels -----------------------------------
__global__ void split_kernel(const float4* __restrict__ src,
                             uint2* __restrict__ dhi, uint2* __restrict__ dlo, int n4)
{
    int i = blockIdx.x * blockDim.x + threadIdx.x;
    if (i >= n4) return;
    float4 v = src[i];
    uint2 hh, ll;
    hh.x = pack_split_hi(v.x, v.y, ll.x);
    hh.y = pack_split_hi(v.z, v.w, ll.y);
    dhi[i] = hh; dlo[i] = ll;
}

__global__ void copy_g2_kernel(const uint4* __restrict__ sh, const uint4* __restrict__ sl,
                               uint4* __restrict__ dh, uint4* __restrict__ dl, int n16)
{
    int i = blockIdx.x * blockDim.x + threadIdx.x;
    if (i < n16) { dh[i] = sh[i]; dl[i] = sl[i]; }
}

__global__ void reduce_params(const float* __restrict__ gpart, float* __restrict__ params)
{
    int row = blockIdx.x * 256 + threadIdx.x;
    float m = 0.f, g = 0.f;
    #pragma unroll
    for (int b = 0; b < 8; b++) {
        m += gpart[row * 16 + b * 2 + 0];
        g += gpart[row * 16 + b * 2 + 1];
    }
    float mu  = 1.f / (1.f + __expf(-m));
    float sp  = (g > 20.f) ? g : log1pf(__expf(g));
    float var = fmaxf(sp, 1e-4f);
    float sv0 = var + 2.5e-5f;
    float sv1 = var + 1.0e-4f;
    params[row * 8 + 0] = mu;
    params[row * 8 + 1] = rsqrtf(6.28318530717958648f * sv0);
    params[row * 8 + 2] = -0.5f / sv0;
    params[row * 8 + 3] = rsqrtf(6.28318530717958648f * sv1);
    params[row * 8 + 4] = -0.5f / sv1;
}

// ------------------------- HMMA split GEMM body (512 threads) --------------
static const int ROWB   = 80;
static const int TILE_B = 128 * ROWB;
static const int OFF_AH = 0, OFF_AL = TILE_B, OFF_BH = 2*TILE_B, OFF_BL = 3*TILE_B;
static const int STAGE_B = 4 * TILE_B;        // 40960
static const int SMEM_BYTES = 2 * STAGE_B;    // 81920
static const int NT = 512;

template<int OUT_MODE>
__device__ __forceinline__
void mma_body(char* dsm, int bx, int by, int bz,
              const bf16* __restrict__ Ah, const bf16* __restrict__ Al, int lda, long long sA,
              const bf16* __restrict__ Bh, const bf16* __restrict__ Bl, int ldb, long long sB,
              float* __restrict__ C, bf16* __restrict__ Ch, bf16* __restrict__ Cl,
              int ldc, long long sC, int K, float alpha,
              const float* __restrict__ wmu, const float* __restrict__ wsg,
              float* __restrict__ gpart)
{
    const uint32_t sb = smem_u32(dsm);
    const int tid = threadIdx.x, lane = tid & 31, wid = tid >> 5;
    const int warp_m = wid >> 2, warp_n = wid & 3;   // 4x4 warp grid, 32x32 tiles

    const bf16* A0h = Ah + (long long)bz * sA + (long long)(by * 128) * lda;
    const bf16* A0l = Al + (long long)bz * sA + (long long)(by * 128) * lda;
    const bf16* B0h = Bh + (long long)bz * sB + (long long)(bx * 128) * ldb;
    const bf16* B0l = Bl + (long long)bz * sB + (long long)(bx * 128) * ldb;

    // per-plane: 512 chunks of 16B; tid -> (row, q)
    const int rr = tid >> 2, qq = tid & 3;
    const uint32_t soff = (uint32_t)(rr * ROWB + qq * 16);
    const long long gAo = (long long)rr * lda + qq * 8;
    const long long gBo = (long long)rr * ldb + qq * 8;

    auto load_stage = [&](int s, int k0) {
        uint32_t d = sb + s * STAGE_B;
        CP_ASYNC16(d + OFF_AH + soff, A0h + gAo + k0);
        CP_ASYNC16(d + OFF_AL + soff, A0l + gAo + k0);
        CP_ASYNC16(d + OFF_BH + soff, B0h + gBo + k0);
        CP_ASYNC16(d + OFF_BL + soff, B0l + gBo + k0);
    };

    const int lr = lane & 15;
    const uint32_t lc = (uint32_t)((lane >> 4) * 16);
    uint32_t aoff[2], boff[2];
    #pragma unroll
    for (int mt = 0; mt < 2; mt++)
        aoff[mt] = (uint32_t)((warp_m * 32 + mt * 16 + lr) * ROWB) + lc;
    #pragma unroll
    for (int n2 = 0; n2 < 2; n2++)
        boff[n2] = (uint32_t)((warp_n * 32 + n2 * 16 + lr) * ROWB) + lc;

    float acc[2][4][4];
    #pragma unroll
    for (int i = 0; i < 2; i++)
        #pragma unroll
        for (int j = 0; j < 4; j++)
            #pragma unroll
            for (int v = 0; v < 4; v++) acc[i][j][v] = 0.f;

    const int nk = K >> 5;
    load_stage(0, 0);
    CP_COMMIT();

    for (int t = 0; t < nk; t++) {
        if (t + 1 < nk) { load_stage((t + 1) & 1, (t + 1) << 5); CP_COMMIT(); CP_WAIT_1(); }
        else            { CP_WAIT_0(); }
        __syncthreads();

        const uint32_t s = sb + (t & 1) * STAGE_B;
        #pragma unroll
        for (int k16 = 0; k16 < 2; k16++) {
            const uint32_t kb = (uint32_t)(k16 * 32);
            uint32_t ah[2][4], al[2][4], bh[2][4], bl[2][4];
            #pragma unroll
            for (int mt = 0; mt < 2; mt++) ldsm4(ah[mt], s + OFF_AH + aoff[mt] + kb);
            #pragma unroll
            for (int n2 = 0; n2 < 2; n2++) ldsm4(bh[n2], s + OFF_BH + boff[n2] + kb);
            #pragma unroll
            for (int mt = 0; mt < 2; mt++)
                #pragma unroll
                for (int nt = 0; nt < 4; nt++) {
                    const uint32_t* b = bh[nt >> 1];
                    mma16816(acc[mt][nt], ah[mt][0], ah[mt][1], ah[mt][2], ah[mt][3],
                             (nt & 1) ? b[1] : b[0], (nt & 1) ? b[3] : b[2]);
                }
            #pragma unroll
            for (int n2 = 0; n2 < 2; n2++) ldsm4(bl[n2], s + OFF_BL + boff[n2] + kb);
            #pragma unroll
            for (int mt = 0; mt < 2; mt++)
                #pragma unroll
                for (int nt = 0; nt < 4; nt++) {
                    const uint32_t* b = bl[nt >> 1];
                    mma16816(acc[mt][nt], ah[mt][0], ah[mt][1], ah[mt][2], ah[mt][3],
                             (nt & 1) ? b[1] : b[0], (nt & 1) ? b[3] : b[2]);
                }
            #pragma unroll
            for (int mt = 0; mt < 2; mt++) ldsm4(al[mt], s + OFF_AL + aoff[mt] + kb);
            #pragma unroll
            for (int mt = 0; mt < 2; mt++)
                #pragma unroll
                for (int nt = 0; nt < 4; nt++) {
                    const uint32_t* b = bh[nt >> 1];
                    mma16816(acc[mt][nt], al[mt][0], al[mt][1], al[mt][2], al[mt][3],
                             (nt & 1) ? b[1] : b[0], (nt & 1) ? b[3] : b[2]);
                }
        }
        __syncthreads();
    }

    const int group = lane >> 2, tig = lane & 3;
    if (OUT_MODE == 2) {
        float pmu[4], psg[4];
        #pragma unroll
        for (int i = 0; i < 4; i++) { pmu[i] = 0.f; psg[i] = 0.f; }
        #pragma unroll
        for (int mt = 0; mt < 2; mt++)
            #pragma unroll
            for (int nt = 0; nt < 4; nt++) {
                int c = bx * 128 + warp_n * 32 + nt * 8 + tig * 2;
                float w0m = wmu[c], w1m = wmu[c + 1];
                float w0s = wsg[c], w1s = wsg[c + 1];
                pmu[mt * 2 + 0] += acc[mt][nt][0] * w0m + acc[mt][nt][1] * w1m;
                pmu[mt * 2 + 1] += acc[mt][nt][2] * w0m + acc[mt][nt][3] * w1m;
                psg[mt * 2 + 0] += acc[mt][nt][0] * w0s + acc[mt][nt][1] * w1s;
                psg[mt * 2 + 1] += acc[mt][nt][2] * w0s + acc[mt][nt][3] * w1s;
            }
        #pragma unroll
        for (int o = 1; o <= 2; o <<= 1)
            #pragma unroll
            for (int i = 0; i < 4; i++) {
                pmu[i] += __shfl_xor_sync(0xffffffffu, pmu[i], o);
                psg[i] += __shfl_xor_sync(0xffffffffu, psg[i], o);
            }
        float* sp = (float*)dsm;          // [128][4][2]
        __syncthreads();
        if (tig == 0) {
            #pragma unroll
            for (int mt = 0; mt < 2; mt++) {
                int ra = warp_m * 32 + mt * 16 + group;
                sp[(ra * 4 + warp_n) * 2 + 0] = pmu[mt * 2 + 0];
                sp[(ra * 4 + warp_n) * 2 + 1] = psg[mt * 2 + 0];
                sp[((ra + 8) * 4 + warp_n) * 2 + 0] = pmu[mt * 2 + 1];
                sp[((ra + 8) * 4 + warp_n) * 2 + 1] = psg[mt * 2 + 1];
            }
        }
        __syncthreads();
        if (tid < 128) {
            float m = 0.f, g = 0.f;
            #pragma unroll
            for (int w = 0; w < 4; w++) {
                m += sp[(tid * 4 + w) * 2 + 0];
                g += sp[(tid * 4 + w) * 2 + 1];
            }
            long long ridx = ((long long)(bz * 16 + by) * 128 + tid);
            gpart[ridx * 16 + bx * 2 + 0] = m * alpha;
            gpart[ridx * 16 + bx * 2 + 1] = g * alpha;
        }
        return;
    }

    #pragma unroll
    for (int mt = 0; mt < 2; mt++) {
        #pragma unroll
        for (int nt = 0; nt < 4; nt++) {
            int row = by * 128 + warp_m * 32 + mt * 16 + group;
            int col = bx * 128 + warp_n * 32 + nt * 8 + tig * 2;
            float v0 = alpha * acc[mt][nt][0], v1 = alpha * acc[mt][nt][1];
            float v2 = alpha * acc[mt][nt][2], v3 = alpha * acc[mt][nt][3];
            if (OUT_MODE == 0) {
                float* p0 = C + (long long)bz * sC + (long long)row * ldc + col;
                float* p1 = p0 + 8LL * ldc;
                *(float2*)p0 = make_float2(v0, v1);
                *(float2*)p1 = make_float2(v2, v3);
            } else {
                long long o0 = (long long)bz * sC + (long long)row * ldc + col;
                long long o1 = o0 + 8LL * ldc;
                uint32_t lo0, lo1;
                uint32_t hi0 = pack_split_hi(v0, v1, lo0);
                uint32_t hi1 = pack_split_hi(v2, v3, lo1);
                *(uint32_t*)(Ch + o0) = hi0;
                *(uint32_t*)(Cl + o0) = lo0;
                *(uint32_t*)(Ch + o1) = hi1;
                *(uint32_t*)(Cl + o1) = lo1;
            }
        }
    }
}

template<int OUT_MODE>
__global__ __launch_bounds__(NT, 1)
void mma_gemm(const bf16* __restrict__ Ah, const bf16* __restrict__ Al, int lda, long long sA,
              const bf16* __restrict__ Bh, const bf16* __restrict__ Bl, int ldb, long long sB,
              float* __restrict__ C, bf16* __restrict__ Ch, bf16* __restrict__ Cl,
              int ldc, long long sC, int K, float alpha,
              const float* __restrict__ wmu, const float* __restrict__ wsg,
              float* __restrict__ gpart)
{
    extern __shared__ char dsm[];
    mma_body<OUT_MODE>(dsm, blockIdx.x, blockIdx.y, blockIdx.z,
                       Ah, Al, lda, sA, Bh, Bl, ldb, sB,
                       C, Ch, Cl, ldc, sC, K, alpha, wmu, wsg, gpart);
}

// Fused GEMM2a + GEMM2b
__global__ __launch_bounds__(NT, 1)
void gemm2_fused(const bf16* __restrict__ G2h, const bf16* __restrict__ G2l,
                 const bf16* __restrict__ KVth, const bf16* __restrict__ KVtl,
                 bf16* __restrict__ keysh, bf16* __restrict__ keysl,
                 bf16* __restrict__ valTh, bf16* __restrict__ valTl)
{
    extern __shared__ char dsm[];
    int id = blockIdx.x;
    if (id < 128) {
        mma_body<1>(dsm, id & 15, id >> 4, 0,
                    G2h, G2l, 512, 0, KVth, KVtl, 512, 0,
                    nullptr, keysh, keysl, 2048, 0,
                    512, 1.0f, nullptr, nullptr, nullptr);
    } else {
        int j = id - 128;
        mma_body<1>(dsm, j & 7, j >> 3, 0,
                    KVth + 2048LL * 512, KVtl + 2048LL * 512, 512, 0,
                    G2h, G2l, 512, 0,
                    nullptr, valTh, valTl, 1024, 0,
                    512, 1.0f, nullptr, nullptr, nullptr);
    }
}

// ------------------------- analytic-A GEMM (ctx = r · valT^T) --------------
static const int R_SMEM = 2 * (2 * TILE_B);   // 40960

__global__ __launch_bounds__(NT, 1)
void gemm_r(const bf16* __restrict__ Bh, const bf16* __restrict__ Bl,
            const float* __restrict__ params,
            bf16* __restrict__ Ch, bf16* __restrict__ Cl)
{
    extern __shared__ char dsm[];
    const uint32_t sb = smem_u32(dsm);
    const int tid = threadIdx.x, lane = tid & 31, wid = tid >> 5;
    const int warp_m = wid >> 2, warp_n = wid & 3;
    const int by = blockIdx.y, bz = blockIdx.z;
    const int group = lane >> 2, tig = lane & 3;
    const float INV511 = 1.0f / 511.0f;

    const bf16* B0h = Bh + (long long)(bz * 128) * 1024;
    const bf16* B0l = Bl + (long long)(bz * 128) * 1024;

    float mu_[4], c0_[4], h0_[4], c1_[4], h1_[4];
    {
        const long long pbase = (long long)(bz * 2048 + by * 128);
        #pragma unroll
        for (int mt = 0; mt < 2; mt++) {
            int ra = warp_m * 32 + mt * 16 + group;
            const float* p0 = params + (pbase + ra) * 8;
            const float* p1 = params + (pbase + ra + 8) * 8;
            mu_[mt*2+0] = p0[0]; c0_[mt*2+0] = p0[1]; h0_[mt*2+0] = p0[2];
            c1_[mt*2+0] = p0[3]; h1_[mt*2+0] = p0[4];
            mu_[mt*2+1] = p1[0]; c0_[mt*2+1] = p1[1]; h0_[mt*2+1] = p1[2];
            c1_[mt*2+1] = p1[3]; h1_[mt*2+1] = p1[4];
        }
    }

    const int rr = tid >> 2, qq = tid & 3;
    const uint32_t soff = (uint32_t)(rr * ROWB + qq * 16);
    const long long gBo = (long long)rr * 1024 + qq * 8;

    auto load_stage = [&](int s, int k0) {
        uint32_t d = sb + s * (2 * TILE_B);
        CP_ASYNC16(d + soff,          B0h + gBo + k0);
        CP_ASYNC16(d + TILE_B + soff, B0l + gBo + k0);
    };

    const int lr = lane & 15;
    const uint32_t lc = (uint32_t)((lane >> 4) * 16);
    uint32_t boff[2];
    #pragma unroll
    for (int n2 = 0; n2 < 2; n2++)
        boff[n2] = (uint32_t)((warp_n * 32 + n2 * 16 + lr) * ROWB) + lc;

    float acc[2][4][4];
    #pragma unroll
    for (int i = 0; i < 2; i++)
        #pragma unroll
        for (int j = 0; j < 4; j++)
            #pragma unroll
            for (int v = 0; v < 4; v++) acc[i][j][v] = 0.f;

    load_stage(0, 0);
    CP_COMMIT();

    for (int t = 0; t < 32; t++) {
        if (t + 1 < 32) { load_stage((t + 1) & 1, (t + 1) << 5); CP_COMMIT(); CP_WAIT_1(); }
        else            { CP_WAIT_0(); }
        __syncthreads();

        const uint32_t s = sb + (t & 1) * (2 * TILE_B);
        #pragma unroll
        for (int k16 = 0; k16 < 2; k16++) {
            const int kb = t * 32 + k16 * 16;
            const uint32_t kbb = (uint32_t)(k16 * 32);
            uint32_t bh[2][4], bl[2][4];
            #pragma unroll
            for (int n2 = 0; n2 < 2; n2++) {
                ldsm4(bh[n2], s + boff[n2] + kbb);
                ldsm4(bl[n2], s + TILE_B + boff[n2] + kbb);
            }
            const float bmu0 = (float)((kb >> 1) + tig) * INV511;
            const float bmu1 = bmu0 + 4.0f * INV511;
            #pragma unroll
            for (int mt = 0; mt < 2; mt++) {
                uint32_t ah[4], al[4];
                #pragma unroll
                for (int f = 0; f < 4; f++) {
                    const int i = mt * 2 + (f & 1);
                    const float bm = (f < 2) ? bmu0 : bmu1;
                    float d = bm - mu_[i];
                    float t2 = d * d;
                    float ve = c0_[i] * __expf(h0_[i] * t2);
                    float vo = c1_[i] * __expf(h1_[i] * t2);
                    bf16 he = __float2bfloat16(ve), ho = __float2bfloat16(vo);
                    __nv_bfloat162 hh = {he, ho};
                    __nv_bfloat162 ll = {__float2bfloat16(ve - __bfloat162float(he)),
                                         __float2bfloat16(vo - __bfloat162float(ho))};
                    ah[f] = *(uint32_t*)&hh;
                    al[f] = *(uint32_t*)&ll;
                }
                #pragma unroll
                for (int nt = 0; nt < 4; nt++) {
                    const uint32_t* b = bh[nt >> 1];
                    uint32_t b0 = (nt & 1) ? b[1] : b[0], b1 = (nt & 1) ? b[3] : b[2];
                    mma16816(acc[mt][nt], ah[0], ah[1], ah[2], ah[3], b0, b1);
                    const uint32_t* bb = bl[nt >> 1];
                    uint32_t c0b = (nt & 1) ? bb[1] : bb[0], c1b = (nt & 1) ? bb[3] : bb[2];
                    mma16816(acc[mt][nt], ah[0], ah[1], ah[2], ah[3], c0b, c1b);
                    mma16816(acc[mt][nt], al[0], al[1], al[2], al[3], b0, b1);
                }
            }
        }
        __syncthreads();
    }

    #pragma unroll
    for (int mt = 0; mt < 2; mt++) {
        #pragma unroll
        for (int nt = 0; nt < 4; nt++) {
            int row = by * 128 + warp_m * 32 + mt * 16 + group;
            int col = bz * 128 + warp_n * 32 + nt * 8 + tig * 2;
            long long o0 = (long long)row * 2048 + col;
            long long o1 = o0 + 8LL * 2048;
            uint32_t lo0, lo1;
            uint32_t hi0 = pack_split_hi(acc[mt][nt][0], acc[mt][nt][1], lo0);
            uint32_t hi1 = pack_split_hi(acc[mt][nt][2], acc[mt][nt][3], lo1);
            *(uint32_t*)(Ch + o0) = hi0;
            *(uint32_t*)(Cl + o0) = lo0;
            *(uint32_t*)(Ch + o1) = hi1;
            *(uint32_t*)(Cl + o1) = lo1;
        }
    }
}

// ------------------------- launch ------------------------------------------
extern "C" void kernel_launch(void* const* d_in, const int* in_sizes, int n_in,
                              void* d_out, int out_size)
{
    (void)in_sizes; (void)n_in; (void)out_size;
    const float* dk   = (const float*)d_in[0];
    const float* dq   = (const float*)d_in[1];
    const float* dWk  = (const float*)d_in[2];
    const float* dWv  = (const float*)d_in[3];
    const float* dWo  = (const float*)d_in[4];
    const float* dwmu = (const float*)d_in[5];
    const float* dwsg = (const float*)d_in[6];
    float* dout = (float*)d_out;

    compute_G2_host();

    bf16 *pWh, *pWl, *pkh, *pkl, *pqh, *pql, *pWoh, *pWol, *pG2h, *pG2l;
    bf16 *pKVth, *pKVtl, *pkeysh, *pkeysl, *pvalTh, *pvalTl;
    bf16 *pctxh, *pctxl;
    float *ppart, *pparams;
    cudaGetSymbolAddress((void**)&pWh,   g_Wh);   cudaGetSymbolAddress((void**)&pWl,   g_Wl);
    cudaGetSymbolAddress((void**)&pkh,   g_kh);   cudaGetSymbolAddress((void**)&pkl,   g_kl);
    cudaGetSymbolAddress((void**)&pqh,   g_qh);   cudaGetSymbolAddress((void**)&pql,   g_ql);
    cudaGetSymbolAddress((void**)&pWoh,  g_Woh);  cudaGetSymbolAddress((void**)&pWol,  g_Wol);
    cudaGetSymbolAddress((void**)&pG2h,  g_G2h);  cudaGetSymbolAddress((void**)&pG2l,  g_G2l);
    cudaGetSymbolAddress((void**)&pKVth, g_KVth); cudaGetSymbolAddress((void**)&pKVtl, g_KVtl);
    cudaGetSymbolAddress((void**)&pkeysh,g_keysh);cudaGetSymbolAddress((void**)&pkeysl,g_keysl);
    cudaGetSymbolAddress((void**)&pvalTh,g_valTh);cudaGetSymbolAddress((void**)&pvalTl,g_valTl);
    cudaGetSymbolAddress((void**)&pctxh, g_ctxh); cudaGetSymbolAddress((void**)&pctxl, g_ctxl);
    cudaGetSymbolAddress((void**)&ppart, g_part); cudaGetSymbolAddress((void**)&pparams, g_params);

    cudaFuncSetAttribute(mma_gemm<0>, cudaFuncAttributeMaxDynamicSharedMemorySize, SMEM_BYTES);
    cudaFuncSetAttribute(mma_gemm<1>, cudaFuncAttributeMaxDynamicSharedMemorySize, SMEM_BYTES);
    cudaFuncSetAttribute(mma_gemm<2>, cudaFuncAttributeMaxDynamicSharedMemorySize, SMEM_BYTES);
    cudaFuncSetAttribute(gemm2_fused, cudaFuncAttributeMaxDynamicSharedMemorySize, SMEM_BYTES);
    cudaFuncSetAttribute(gemm_r,      cudaFuncAttributeMaxDynamicSharedMemorySize, R_SMEM);

    {
        int n4 = 2048 * 2048 / 4;
        split_kernel<<<(n4 + 255) / 256, 256>>>((const float4*)dWk, (uint2*)pWh, (uint2*)pWl, n4);
        split_kernel<<<(n4 + 255) / 256, 256>>>((const float4*)dWv,
                                                (uint2*)(pWh + 2048 * 2048), (uint2*)(pWl + 2048 * 2048), n4);
        int nk4 = 512 * 2048 / 4;
        split_kernel<<<(nk4 + 255) / 256, 256>>>((const float4*)dk, (uint2*)pkh, (uint2*)pkl, nk4);
        int n16 = 1024 * 512 * 2 / 16;
        copy_g2_kernel<<<(n16 + 255) / 256, 256>>>((const uint4*)hG2h, (const uint4*)hG2l,
                                                   (uint4*)pG2h, (uint4*)pG2l, n16);
        int nq4 = 16 * 2048 * 128 / 4;
        split_kernel<<<(nq4 + 255) / 256, 256>>>((const float4*)dq, (uint2*)pqh, (uint2*)pql, nq4);
    }

    // 1: KVt[z*2048+j][l] = W[z][j]·k[l]
    {
        dim3 g(4, 16, 2);
        mma_gemm<1><<<g, NT, SMEM_BYTES>>>(pWh, pWl, 2048, 2048LL * 2048,
                                           pkh, pkl, 2048, 0,
                                           nullptr, pKVth, pKVtl, 512, 2048LL * 512,
                                           2048, 1.0f, nullptr, nullptr, nullptr);
    }
    {
        int n4 = 2048 * 2048 / 4;
        split_kernel<<<(n4 + 255) / 256, 256>>>((const float4*)dWo, (uint2*)pWoh, (uint2*)pWol, n4);
    }
    // 2: fused keys + valT
    gemm2_fused<<<256, NT, SMEM_BYTES>>>(pG2h, pG2l, pKVth, pKVtl,
                                         pkeysh, pkeysl, pvalTh, pvalTl);
    // 3: scores reduced in-register -> per-row partials
    {
        dim3 g(8, 16, 16);
        mma_gemm<2><<<g, NT, SMEM_BYTES>>>(pqh, pql, 128, 2048LL * 128,
                                           pkeysh, pkeysl, 2048, 128,
                                           nullptr, nullptr, nullptr, 0, 0,
                                           128, 0.08838834764831845f, dwmu, dwsg, ppart);
    }
    // 4: fold partials -> row params
    reduce_params<<<128, 256>>>(ppart, pparams);

    // 5: ctx = r · valT^T with analytic A
    {
        dim3 g(1, 16, 16);
        gemm_r<<<g, NT, R_SMEM>>>(pvalTh, pvalTl, pparams, pctxh, pctxl);
    }
    // 6: out[q][o] = ctx[q]·Wo[o]
    {
        dim3 g(16, 16, 1);
        mma_gemm<0><<<g, NT, SMEM_BYTES>>>(pctxh, pctxl, 2048, 0,
                                           pWoh, pWol, 2048, 0,
                                           dout, nullptr, nullptr, 2048, 0,
                                           2048, 1.0f, nullptr, nullptr, nullptr);
    }
}

// round 14
// speedup vs baseline: 1.8448x; 1.0844x over previous
#include <cuda_runtime.h>
#include <cuda_bf16.h>
#include <math.h>
#include <string.h>
#include <stdint.h>

// ---------------------------------------------------------------------------
//  H=16, D=128, d=2048, N_BASIS=1024, l=512, QLEN=2048, RIDGE=0.5
//  GEMMs on HMMA (mma.sync m16n8k16 bf16), split-bf16 3-pass for ~fp32.
//  Big-tile kernels: CTA 256x128, 8 warps of 64x64 -> 24 MAC per smem byte
//  (smem crossbar no longer the bottleneck). r staged through smem in gemm_r.
// ---------------------------------------------------------------------------

typedef __nv_bfloat16 bf16;

// ------------------------- device scratch (static) -------------------------
__device__ bf16 g_Wh [2u*2048*2048], g_Wl [2u*2048*2048];
__device__ bf16 g_kh [512*2048],     g_kl [512*2048];
__device__ bf16 g_qh [16*2048*128],  g_ql [16*2048*128];
__device__ bf16 g_Woh[2048*2048],    g_Wol[2048*2048];
__device__ bf16 g_G2h[1024*512],     g_G2l[1024*512];
__device__ bf16 g_KVth[4096*512],    g_KVtl[4096*512];
__device__ bf16 g_keysh[1024*2048],  g_keysl[1024*2048];
__device__ bf16 g_valTh[2048*1024],  g_valTl[2048*1024];
__device__ float g_part[16u*16*128*16];
__device__ float g_params[32768u*8];
__device__ bf16 g_ctxh[2048*2048],   g_ctxl[2048*2048];

// ------------------------- host-side G2 (fp64 solve) -----------------------
static double hF[1024 * 1024];
static double hA[1024 * 1024];
static double hX[1024 * 1024];
static __align__(16) bf16 hG2h[1024 * 512];
static __align__(16) bf16 hG2l[1024 * 512];
static double hbmu[1024], hbsig[1024];
static int    hlo[1024], hhi[1024];

static void compute_G2_host()
{
    const int n = 1024, P = 1024;
    for (int i = 0; i < 512; i++) {
        double m = (double)i / 511.0;
        hbmu[2*i] = m;  hbmu[2*i+1] = m;
        hbsig[2*i] = 0.005; hbsig[2*i+1] = 0.01;
    }
    const double shift = 1.0 / 1024.0;
    const double start = -0.5 + shift, stop = 1.5 - shift;
    const double step  = (stop - start) / (double)(P - 1);
    const double inv_sqrt2pi = 0.39894228040143267794;

    for (int b = 0; b < n; b++) {
        double mu = hbmu[b], sg = hbsig[b];
        double c = inv_sqrt2pi / sg;
        int lo = P, hi = 0;
        for (int p = 0; p < P; p++) {
            double x = start + p * step;
            double t = (x - mu) / sg;
            double v = (fabs(t) < 38.0) ? c * exp(-0.5 * t * t) : 0.0;
            hF[(long)b * P + p] = v;
            if (v != 0.0) { if (p < lo) lo = p; if (p + 1 > hi) hi = p + 1; }
        }
        hlo[b] = lo; hhi[b] = hi;
    }

    memset(hA, 0, sizeof(hA));
    for (int i = 0; i < n; i++) {
        for (int j = i; j < n; j++) {
            int lo = hlo[i] > hlo[j] ? hlo[i] : hlo[j];
            int hi = hhi[i] < hhi[j] ? hhi[i] : hhi[j];
            double s = 0.0;
            if (lo < hi) {
                const double* fi = &hF[(long)i * P];
                const double* fj = &hF[(long)j * P];
                for (int p = lo; p < hi; p++) s += fi[p] * fj[p];
            }
            if (i == j) s += 0.5;
            hA[(long)i * n + j] = s;
            hA[(long)j * n + i] = s;
        }
    }
    for (int i = 0; i < n; i++) {
        for (int j = 0; j <= i; j++) {
            double s = hA[(long)i * n + j];
            const double* Li = &hA[(long)i * n];
            const double* Lj = &hA[(long)j * n];
            for (int k2 = 0; k2 < j; k2++) s -= Li[k2] * Lj[k2];
            if (j == i) hA[(long)i * n + i] = sqrt(s);
            else        hA[(long)i * n + j] = s / hA[(long)j * n + j];
        }
    }
    memcpy(hX, hF, sizeof(hX));
    for (int i = 0; i < n; i++) {
        double* xi = &hX[(long)i * P];
        const double* Li = &hA[(long)i * n];
        for (int k2 = 0; k2 < i; k2++) {
            double l = Li[k2];
            if (l != 0.0) {
                const double* xk = &hX[(long)k2 * P];
                for (int p = 0; p < P; p++) xi[p] -= l * xk[p];
            }
        }
        double inv = 1.0 / hA[(long)i * n + i];
        for (int p = 0; p < P; p++) xi[p] *= inv;
    }
    for (int i = n - 1; i >= 0; i--) {
        double* xi = &hX[(long)i * P];
        for (int k2 = i + 1; k2 < n; k2++) {
            double l = hA[(long)k2 * n + i];
            if (l != 0.0) {
                const double* xk = &hX[(long)k2 * P];
                for (int p = 0; p < P; p++) xi[p] -= l * xk[p];
            }
        }
        double inv = 1.0 / hA[(long)i * n + i];
        for (int p = 0; p < P; p++) xi[p] *= inv;
    }
    for (int b = 0; b < n; b++)
        for (int l = 0; l < 512; l++) {
            float v = (float)hX[(long)b * P + 256 + l];
            bf16 h = __float2bfloat16(v);
            hG2h[b * 512 + l] = h;
            hG2l[b * 512 + l] = __float2bfloat16(v - __bfloat162float(h));
        }
}

// ------------------------- PTX helpers -------------------------------------
__device__ __forceinline__ uint32_t smem_u32(const void* p) {
    uint32_t a;
    asm("{ .reg .u64 t; cvta.to.shared.u64 t, %1; cvt.u32.u64 %0, t; }" : "=r"(a) : "l"(p));
    return a;
}
__device__ __forceinline__ void ldsm4(uint32_t* r, uint32_t addr) {
    asm volatile("ldmatrix.sync.aligned.m8n8.x4.shared.b16 {%0,%1,%2,%3}, [%4];"
                 : "=r"(r[0]), "=r"(r[1]), "=r"(r[2]), "=r"(r[3]) : "r"(addr));
}
__device__ __forceinline__ void mma16816(float* d,
                                         uint32_t a0, uint32_t a1, uint32_t a2, uint32_t a3,
                                         uint32_t b0, uint32_t b1) {
    asm volatile("mma.sync.aligned.m16n8k16.row.col.f32.bf16.bf16.f32 "
                 "{%0,%1,%2,%3}, {%4,%5,%6,%7}, {%8,%9}, {%0,%1,%2,%3};"
                 : "+f"(d[0]), "+f"(d[1]), "+f"(d[2]), "+f"(d[3])
                 : "r"(a0), "r"(a1), "r"(a2), "r"(a3), "r"(b0), "r"(b1));
}
#define CP_ASYNC16(dst, src) \
    asm volatile("cp.async.cg.shared.global [%0], [%1], 16;" :: "r"(dst), "l"(src) : "memory")
#define CP_COMMIT() asm volatile("cp.async.commit_group;" ::: "memory")
#define CP_WAIT_1()  asm volatile("cp.async.wait_group 1;" ::: "memory")
#define CP_WAIT_0()  asm volatile("cp.async.wait_group 0;" ::: "memory")

__device__ __forceinline__ uint32_t pack_split_hi(float v0, float v1, uint32_t& lo) {
    bf16 h0 = __float2bfloat16(v0), h1 = __float2bfloat16(v1);
    __nv_bfloat162 hh = {h0, h1};
    __nv_bfloat162 ll = {__float2bfloat16(v0 - __bfloat162float(h0)),
                         __float2bfloat16(v1 - __bfloat162float(h1))};
    lo = *(uint32_t*)&ll;
    return *(uint32_t*)&hh;
}

// ------------------------- small kernels -----------------------------------
__global__ void split_kernel(const float4* __restrict__ src,
                             uint2* __restrict__ dhi, uint2* __restrict__ dlo, int n4)
{
    int i = blockIdx.x * blockDim.x + threadIdx.x;
    if (i >= n4) return;
    float4 v = src[i];
    uint2 hh, ll;
    hh.x = pack_split_hi(v.x, v.y, ll.x);
    hh.y = pack_split_hi(v.z, v.w, ll.y);
    dhi[i] = hh; dlo[i] = ll;
}

__global__ void copy_g2_kernel(const uint4* __restrict__ sh, const uint4* __restrict__ sl,
                               uint4* __restrict__ dh, uint4* __restrict__ dl, int n16)
{
    int i = blockIdx.x * blockDim.x + threadIdx.x;
    if (i < n16) { dh[i] = sh[i]; dl[i] = sl[i]; }
}

__global__ void reduce_params(const float* __restrict__ gpart, float* __restrict__ params)
{
    int row = blockIdx.x * 256 + threadIdx.x;
    float m = 0.f, g = 0.f;
    #pragma unroll
    for (int b = 0; b < 8; b++) {
        m += gpart[row * 16 + b * 2 + 0];
        g += gpart[row * 16 + b * 2 + 1];
    }
    float mu  = 1.f / (1.f + __expf(-m));
    float sp  = (g > 20.f) ? g : log1pf(__expf(g));
    float var = fmaxf(sp, 1e-4f);
    float sv0 = var + 2.5e-5f;
    float sv1 = var + 1.0e-4f;
    params[row * 8 + 0] = mu;
    params[row * 8 + 1] = rsqrtf(6.28318530717958648f * sv0);
    params[row * 8 + 2] = -0.5f / sv0;
    params[row * 8 + 3] = rsqrtf(6.28318530717958648f * sv1);
    params[row * 8 + 4] = -0.5f / sv1;
}

// ===================== OLD 512-thread kernel (kept for G1) ==================
static const int ROWB   = 80;
static const int TILE_B = 128 * ROWB;
static const int OFF_AH = 0, OFF_AL = TILE_B, OFF_BH = 2*TILE_B, OFF_BL = 3*TILE_B;
static const int STAGE_B = 4 * TILE_B;        // 40960
static const int SMEM_BYTES = 2 * STAGE_B;    // 81920
static const int NT = 512;

__global__ __launch_bounds__(NT, 1)
void mma_gemm1(const bf16* __restrict__ Ah, const bf16* __restrict__ Al, int lda, long long sA,
               const bf16* __restrict__ Bh, const bf16* __restrict__ Bl, int ldb, long long sB,
               bf16* __restrict__ Ch, bf16* __restrict__ Cl,
               int ldc, long long sC, int K)
{
    extern __shared__ char dsm[];
    const uint32_t sb = smem_u32(dsm);
    const int tid = threadIdx.x, lane = tid & 31, wid = tid >> 5;
    const int warp_m = wid >> 2, warp_n = wid & 3;
    const int bx = blockIdx.x, by = blockIdx.y, bz = blockIdx.z;

    const bf16* A0h = Ah + (long long)bz * sA + (long long)(by * 128) * lda;
    const bf16* A0l = Al + (long long)bz * sA + (long long)(by * 128) * lda;
    const bf16* B0h = Bh + (long long)bz * sB + (long long)(bx * 128) * ldb;
    const bf16* B0l = Bl + (long long)bz * sB + (long long)(bx * 128) * ldb;

    const int rr = tid >> 2, qq = tid & 3;
    const uint32_t soff = (uint32_t)(rr * ROWB + qq * 16);
    const long long gAo = (long long)rr * lda + qq * 8;
    const long long gBo = (long long)rr * ldb + qq * 8;

    auto load_stage = [&](int s, int k0) {
        uint32_t d = sb + s * STAGE_B;
        CP_ASYNC16(d + OFF_AH + soff, A0h + gAo + k0);
        CP_ASYNC16(d + OFF_AL + soff, A0l + gAo + k0);
        CP_ASYNC16(d + OFF_BH + soff, B0h + gBo + k0);
        CP_ASYNC16(d + OFF_BL + soff, B0l + gBo + k0);
    };

    const int lr = lane & 15;
    const uint32_t lc = (uint32_t)((lane >> 4) * 16);
    uint32_t aoff[2], boff[2];
    #pragma unroll
    for (int mt = 0; mt < 2; mt++)
        aoff[mt] = (uint32_t)((warp_m * 32 + mt * 16 + lr) * ROWB) + lc;
    #pragma unroll
    for (int n2 = 0; n2 < 2; n2++)
        boff[n2] = (uint32_t)((warp_n * 32 + n2 * 16 + lr) * ROWB) + lc;

    float acc[2][4][4];
    #pragma unroll
    for (int i = 0; i < 2; i++)
        #pragma unroll
        for (int j = 0; j < 4; j++)
            #pragma unroll
            for (int v = 0; v < 4; v++) acc[i][j][v] = 0.f;

    const int nk = K >> 5;
    load_stage(0, 0);
    CP_COMMIT();

    for (int t = 0; t < nk; t++) {
        if (t + 1 < nk) { load_stage((t + 1) & 1, (t + 1) << 5); CP_COMMIT(); CP_WAIT_1(); }
        else            { CP_WAIT_0(); }
        __syncthreads();

        const uint32_t s = sb + (t & 1) * STAGE_B;
        #pragma unroll
        for (int k16 = 0; k16 < 2; k16++) {
            const uint32_t kb = (uint32_t)(k16 * 32);
            uint32_t ah[2][4], al[2][4], bh[2][4], bl[2][4];
            #pragma unroll
            for (int mt = 0; mt < 2; mt++) ldsm4(ah[mt], s + OFF_AH + aoff[mt] + kb);
            #pragma unroll
            for (int n2 = 0; n2 < 2; n2++) ldsm4(bh[n2], s + OFF_BH + boff[n2] + kb);
            #pragma unroll
            for (int mt = 0; mt < 2; mt++)
                #pragma unroll
                for (int nt = 0; nt < 4; nt++) {
                    const uint32_t* b = bh[nt >> 1];
                    mma16816(acc[mt][nt], ah[mt][0], ah[mt][1], ah[mt][2], ah[mt][3],
                             (nt & 1) ? b[1] : b[0], (nt & 1) ? b[3] : b[2]);
                }
            #pragma unroll
            for (int n2 = 0; n2 < 2; n2++) ldsm4(bl[n2], s + OFF_BL + boff[n2] + kb);
            #pragma unroll
            for (int mt = 0; mt < 2; mt++)
                #pragma unroll
                for (int nt = 0; nt < 4; nt++) {
                    const uint32_t* b = bl[nt >> 1];
                    mma16816(acc[mt][nt], ah[mt][0], ah[mt][1], ah[mt][2], ah[mt][3],
                             (nt & 1) ? b[1] : b[0], (nt & 1) ? b[3] : b[2]);
                }
            #pragma unroll
            for (int mt = 0; mt < 2; mt++) ldsm4(al[mt], s + OFF_AL + aoff[mt] + kb);
            #pragma unroll
            for (int mt = 0; mt < 2; mt++)
                #pragma unroll
                for (int nt = 0; nt < 4; nt++) {
                    const uint32_t* b = bh[nt >> 1];
                    mma16816(acc[mt][nt], al[mt][0], al[mt][1], al[mt][2], al[mt][3],
                             (nt & 1) ? b[1] : b[0], (nt & 1) ? b[3] : b[2]);
                }
        }
        __syncthreads();
    }

    const int group = lane >> 2, tig = lane & 3;
    #pragma unroll
    for (int mt = 0; mt < 2; mt++) {
        #pragma unroll
        for (int nt = 0; nt < 4; nt++) {
            int row = by * 128 + warp_m * 32 + mt * 16 + group;
            int col = bx * 128 + warp_n * 32 + nt * 8 + tig * 2;
            long long o0 = (long long)bz * sC + (long long)row * ldc + col;
            long long o1 = o0 + 8LL * ldc;
            uint32_t lo0, lo1;
            uint32_t hi0 = pack_split_hi(acc[mt][nt][0], acc[mt][nt][1], lo0);
            uint32_t hi1 = pack_split_hi(acc[mt][nt][2], acc[mt][nt][3], lo1);
            *(uint32_t*)(Ch + o0) = hi0;
            *(uint32_t*)(Cl + o0) = lo0;
            *(uint32_t*)(Ch + o1) = hi1;
            *(uint32_t*)(Cl + o1) = lo1;
        }
    }
}

// ===================== BIG kernel: CTA 256x128, 8 warps of 64x64 ============
static const int OFFB_AL = 256 * ROWB;        // 20480
static const int OFFB_BH = 512 * ROWB;        // 40960
static const int OFFB_BL = 640 * ROWB;        // 51200
static const int STAGE_BIG = 768 * ROWB;      // 61440
static const int SMEM_BIG = 2 * STAGE_BIG;    // 122880

// OUT_MODE 0: fp32 C; 1: split bf16 (Ch, Cl); 2: mu/sg per-row partials
template<int OUT_MODE>
__device__ __forceinline__
void big_body(char* dsm, int bx, int by, int bz,
              const bf16* __restrict__ Ah, const bf16* __restrict__ Al, int lda, long long sA,
              const bf16* __restrict__ Bh, const bf16* __restrict__ Bl, int ldb, long long sB,
              float* __restrict__ C, bf16* __restrict__ Ch, bf16* __restrict__ Cl,
              int ldc, long long sC, int K, float alpha,
              const float* __restrict__ wmu, const float* __restrict__ wsg,
              float* __restrict__ gpart)
{
    const uint32_t sb = smem_u32(dsm);
    const int tid = threadIdx.x, lane = tid & 31, wid = tid >> 5;
    const int warp_m = wid >> 1, warp_n = wid & 1;   // 4x2 grid of 64x64 tiles

    const bf16* A0h = Ah + (long long)bz * sA + (long long)(by * 256) * lda;
    const bf16* A0l = Al + (long long)bz * sA + (long long)(by * 256) * lda;
    const bf16* B0h = Bh + (long long)bz * sB + (long long)(bx * 128) * ldb;
    const bf16* B0l = Bl + (long long)bz * sB + (long long)(bx * 128) * ldb;

    const int r0 = tid >> 2;                  // 0..63
    const int q8 = (tid & 3) * 8;
    const uint32_t soff = (uint32_t)(r0 * ROWB + (tid & 3) * 16);

    auto load_stage = [&](int s, int k0) {
        uint32_t d = sb + s * STAGE_BIG + soff;
        #pragma unroll
        for (int i = 0; i < 4; i++)
            CP_ASYNC16(d + i * (64*ROWB), A0h + (long long)(r0 + i*64) * lda + k0 + q8);
        #pragma unroll
        for (int i = 0; i < 4; i++)
            CP_ASYNC16(d + OFFB_AL + i * (64*ROWB), A0l + (long long)(r0 + i*64) * lda + k0 + q8);
        #pragma unroll
        for (int i = 0; i < 2; i++)
            CP_ASYNC16(d + OFFB_BH + i * (64*ROWB), B0h + (long long)(r0 + i*64) * ldb + k0 + q8);
        #pragma unroll
        for (int i = 0; i < 2; i++)
            CP_ASYNC16(d + OFFB_BL + i * (64*ROWB), B0l + (long long)(r0 + i*64) * ldb + k0 + q8);
    };

    const int lr = lane & 15;
    const uint32_t lc = (uint32_t)((lane >> 4) * 16);
    uint32_t aoff[4], boff[4];
    #pragma unroll
    for (int mt = 0; mt < 4; mt++)
        aoff[mt] = (uint32_t)((warp_m * 64 + mt * 16 + lr) * ROWB) + lc;
    #pragma unroll
    for (int n2 = 0; n2 < 4; n2++)
        boff[n2] = (uint32_t)((warp_n * 64 + n2 * 16 + lr) * ROWB) + lc;

    float acc[4][8][4];
    #pragma unroll
    for (int i = 0; i < 4; i++)
        #pragma unroll
        for (int j = 0; j < 8; j++)
            #pragma unroll
            for (int v = 0; v < 4; v++) acc[i][j][v] = 0.f;

    const int nk = K >> 5;
    load_stage(0, 0);
    CP_COMMIT();

    for (int t = 0; t < nk; t++) {
        if (t + 1 < nk) { load_stage((t + 1) & 1, (t + 1) << 5); CP_COMMIT(); CP_WAIT_1(); }
        else            { CP_WAIT_0(); }
        __syncthreads();

        const uint32_t s = sb + (t & 1) * STAGE_BIG;
        #pragma unroll
        for (int k16 = 0; k16 < 2; k16++) {
            const uint32_t kb = (uint32_t)(k16 * 32);
            uint32_t ah[4][4], al[4][4], bh[4][4], bl[4][4];
            #pragma unroll
            for (int mt = 0; mt < 4; mt++) ldsm4(ah[mt], s + aoff[mt] + kb);
            #pragma unroll
            for (int n2 = 0; n2 < 4; n2++) ldsm4(bh[n2], s + OFFB_BH + boff[n2] + kb);
            #pragma unroll
            for (int mt = 0; mt < 4; mt++)
                #pragma unroll
                for (int nt = 0; nt < 8; nt++) {
                    const uint32_t* b = bh[nt >> 1];
                    mma16816(acc[mt][nt], ah[mt][0], ah[mt][1], ah[mt][2], ah[mt][3],
                             (nt & 1) ? b[1] : b[0], (nt & 1) ? b[3] : b[2]);
                }
            #pragma unroll
            for (int n2 = 0; n2 < 4; n2++) ldsm4(bl[n2], s + OFFB_BL + boff[n2] + kb);
            #pragma unroll
            for (int mt = 0; mt < 4; mt++)
                #pragma unroll
                for (int nt = 0; nt < 8; nt++) {
                    const uint32_t* b = bl[nt >> 1];
                    mma16816(acc[mt][nt], ah[mt][0], ah[mt][1], ah[mt][2], ah[mt][3],
                             (nt & 1) ? b[1] : b[0], (nt & 1) ? b[3] : b[2]);
                }
            #pragma unroll
            for (int mt = 0; mt < 4; mt++) ldsm4(al[mt], s + OFFB_AL + aoff[mt] + kb);
            #pragma unroll
            for (int mt = 0; mt < 4; mt++)
                #pragma unroll
                for (int nt = 0; nt < 8; nt++) {
                    const uint32_t* b = bh[nt >> 1];
                    mma16816(acc[mt][nt], al[mt][0], al[mt][1], al[mt][2], al[mt][3],
                             (nt & 1) ? b[1] : b[0], (nt & 1) ? b[3] : b[2]);
                }
        }
        __syncthreads();
    }

    const int group = lane >> 2, tig = lane & 3;
    if (OUT_MODE == 2) {
        // per-row partial dots with wmu/wsg over this CTA's 128 cols
        float pmu[8], psg[8];
        #pragma unroll
        for (int i = 0; i < 8; i++) { pmu[i] = 0.f; psg[i] = 0.f; }
        #pragma unroll
        for (int mt = 0; mt < 4; mt++)
            #pragma unroll
            for (int nt = 0; nt < 8; nt++) {
                int c = bx * 128 + warp_n * 64 + nt * 8 + tig * 2;
                float w0m = wmu[c], w1m = wmu[c + 1];
                float w0s = wsg[c], w1s = wsg[c + 1];
                pmu[mt * 2 + 0] += acc[mt][nt][0] * w0m + acc[mt][nt][1] * w1m;
                pmu[mt * 2 + 1] += acc[mt][nt][2] * w0m + acc[mt][nt][3] * w1m;
                psg[mt * 2 + 0] += acc[mt][nt][0] * w0s + acc[mt][nt][1] * w1s;
                psg[mt * 2 + 1] += acc[mt][nt][2] * w0s + acc[mt][nt][3] * w1s;
            }
        #pragma unroll
        for (int o = 1; o <= 2; o <<= 1)
            #pragma unroll
            for (int i = 0; i < 8; i++) {
                pmu[i] += __shfl_xor_sync(0xffffffffu, pmu[i], o);
                psg[i] += __shfl_xor_sync(0xffffffffu, psg[i], o);
            }
        float* sp = (float*)dsm;          // [256 rows][2 warp_n][2 comp]
        __syncthreads();
        if (tig == 0) {
            #pragma unroll
            for (int mt = 0; mt < 4; mt++) {
                int ra = warp_m * 64 + mt * 16 + group;
                sp[(ra * 2 + warp_n) * 2 + 0] = pmu[mt * 2 + 0];
                sp[(ra * 2 + warp_n) * 2 + 1] = psg[mt * 2 + 0];
                sp[((ra + 8) * 2 + warp_n) * 2 + 0] = pmu[mt * 2 + 1];
                sp[((ra + 8) * 2 + warp_n) * 2 + 1] = psg[mt * 2 + 1];
            }
        }
        __syncthreads();
        {
            float m = sp[(tid * 2 + 0) * 2 + 0] + sp[(tid * 2 + 1) * 2 + 0];
            float g = sp[(tid * 2 + 0) * 2 + 1] + sp[(tid * 2 + 1) * 2 + 1];
            long long ridx = ((long long)bz * 2048 + by * 256 + tid);
            gpart[ridx * 16 + bx * 2 + 0] = m * alpha;
            gpart[ridx * 16 + bx * 2 + 1] = g * alpha;
        }
        return;
    }

    #pragma unroll
    for (int mt = 0; mt < 4; mt++) {
        #pragma unroll
        for (int nt = 0; nt < 8; nt++) {
            int row = by * 256 + warp_m * 64 + mt * 16 + group;
            int col = bx * 128 + warp_n * 64 + nt * 8 + tig * 2;
            float v0 = alpha * acc[mt][nt][0], v1 = alpha * acc[mt][nt][1];
            float v2 = alpha * acc[mt][nt][2], v3 = alpha * acc[mt][nt][3];
            if (OUT_MODE == 0) {
                float* p0 = C + (long long)bz * sC + (long long)row * ldc + col;
                float* p1 = p0 + 8LL * ldc;
                *(float2*)p0 = make_float2(v0, v1);
                *(float2*)p1 = make_float2(v2, v3);
            } else {
                long long o0 = (long long)bz * sC + (long long)row * ldc + col;
                long long o1 = o0 + 8LL * ldc;
                uint32_t lo0, lo1;
                uint32_t hi0 = pack_split_hi(v0, v1, lo0);
                uint32_t hi1 = pack_split_hi(v2, v3, lo1);
                *(uint32_t*)(Ch + o0) = hi0;
                *(uint32_t*)(Cl + o0) = lo0;
                *(uint32_t*)(Ch + o1) = hi1;
                *(uint32_t*)(Cl + o1) = lo1;
            }
        }
    }
}

template<int OUT_MODE>
__global__ __launch_bounds__(256)
void mma_big(const bf16* __restrict__ Ah, const bf16* __restrict__ Al, int lda, long long sA,
             const bf16* __restrict__ Bh, const bf16* __restrict__ Bl, int ldb, long long sB,
             float* __restrict__ C, bf16* __restrict__ Ch, bf16* __restrict__ Cl,
             int ldc, long long sC, int K, float alpha,
             const float* __restrict__ wmu, const float* __restrict__ wsg,
             float* __restrict__ gpart)
{
    extern __shared__ char dsm[];
    big_body<OUT_MODE>(dsm, blockIdx.x, blockIdx.y, blockIdx.z,
                       Ah, Al, lda, sA, Bh, Bl, ldb, sB,
                       C, Ch, Cl, ldc, sC, K, alpha, wmu, wsg, gpart);
}

// Fused GEMM2a + GEMM2b on big tiles (64 + 64 = 128 CTAs, one full wave)
__global__ __launch_bounds__(256)
void gemm2_fused_big(const bf16* __restrict__ G2h, const bf16* __restrict__ G2l,
                     const bf16* __restrict__ KVth, const bf16* __restrict__ KVtl,
                     bf16* __restrict__ keysh, bf16* __restrict__ keysl,
                     bf16* __restrict__ valTh, bf16* __restrict__ valTl)
{
    extern __shared__ char dsm[];
    int id = blockIdx.x;
    if (id < 64) {
        // 2a: keys[n][j] = G2[n]·KVt_key[j]   M=1024 (4 tiles), N=2048 (16)
        big_body<1>(dsm, id & 15, id >> 4, 0,
                    G2h, G2l, 512, 0, KVth, KVtl, 512, 0,
                    nullptr, keysh, keysl, 2048, 0,
                    512, 1.0f, nullptr, nullptr, nullptr);
    } else {
        // 2b: valT[j][n] = KVt_val[j]·G2[n]   M=2048 (8 tiles), N=1024 (8)
        int j = id - 64;
        big_body<1>(dsm, j & 7, j >> 3, 0,
                    KVth + 2048LL * 512, KVtl + 2048LL * 512, 512, 0,
                    G2h, G2l, 512, 0,
                    nullptr, valTh, valTl, 1024, 0,
                    512, 1.0f, nullptr, nullptr, nullptr);
    }
}

// ---------------- gemm_r big: ctx = r · valT^T, r staged through smem ------
// A (r) produced analytically into the stage buffer's A region (one row per
// thread per stage), so exp work is done once instead of once per warp_n.
__global__ __launch_bounds__(256)
void gemm_r_big(const bf16* __restrict__ Bh, const bf16* __restrict__ Bl,
                const float* __restrict__ params,
                bf16* __restrict__ Ch, bf16* __restrict__ Cl)
{
    extern __shared__ char dsm[];
    const uint32_t sb = smem_u32(dsm);
    const int tid = threadIdx.x, lane = tid & 31, wid = tid >> 5;
    const int warp_m = wid >> 1, warp_n = wid & 1;
    const int by = blockIdx.y, bz = blockIdx.z;
    const float INV511 = 1.0f / 511.0f;

    const bf16* B0h = Bh + (long long)(bz * 128) * 1024;
    const bf16* B0l = Bl + (long long)(bz * 128) * 1024;

    // this thread produces r for one row of the 256-row tile
    float mu_, c0_, h0_, c1_, h1_;
    {
        const float* p = params + ((long long)bz * 2048 + by * 256 + tid) * 8;
        mu_ = p[0]; c0_ = p[1]; h0_ = p[2]; c1_ = p[3]; h1_ = p[4];
    }

    // B cp.async mapping
    const int r0 = tid >> 2;
    const int q8 = (tid & 3) * 8;
    const uint32_t soff = (uint32_t)(r0 * ROWB + (tid & 3) * 16);

    auto load_B = [&](int s, int k0) {
        uint32_t d = sb + s * STAGE_BIG + soff;
        #pragma unroll
        for (int i = 0; i < 2; i++)
            CP_ASYNC16(d + OFFB_BH + i * (64*ROWB), B0h + (long long)(r0 + i*64) * 1024 + k0 + q8);
        #pragma unroll
        for (int i = 0; i < 2; i++)
            CP_ASYNC16(d + OFFB_BL + i * (64*ROWB), B0l + (long long)(r0 + i*64) * 1024 + k0 + q8);
    };

    // produce r[row][k0..k0+31] split into (hi, lo) in stage s A regions
    auto produce_r = [&](int s, int k0) {
        char* base = dsm + s * STAGE_BIG + tid * ROWB;
        #pragma unroll
        for (int cp = 0; cp < 16; cp++) {
            float bmu = (float)((k0 >> 1) + cp) * INV511;
            float d = bmu - mu_;
            float t2 = d * d;
            float ve = c0_ * __expf(h0_ * t2);   // even col
            float vo = c1_ * __expf(h1_ * t2);   // odd col
            uint32_t lo;
            uint32_t hi = pack_split_hi(ve, vo, lo);
            *(uint32_t*)(base + cp * 4) = hi;
            *(uint32_t*)(base + OFFB_AL + cp * 4) = lo;
        }
    };

    const int lr = lane & 15;
    const uint32_t lc = (uint32_t)((lane >> 4) * 16);
    uint32_t aoff[4], boff[4];
    #pragma unroll
    for (int mt = 0; mt < 4; mt++)
        aoff[mt] = (uint32_t)((warp_m * 64 + mt * 16 + lr) * ROWB) + lc;
    #pragma unroll
    for (int n2 = 0; n2 < 4; n2++)
        boff[n2] = (uint32_t)((warp_n * 64 + n2 * 16 + lr) * ROWB) + lc;

    float acc[4][8][4];
    #pragma unroll
    for (int i = 0; i < 4; i++)
        #pragma unroll
        for (int j = 0; j < 8; j++)
            #pragma unroll
            for (int v = 0; v < 4; v++) acc[i][j][v] = 0.f;

    const int nk = 32;    // K = 1024
    produce_r(0, 0);
    load_B(0, 0);
    CP_COMMIT();

    for (int t = 0; t < nk; t++) {
        if (t + 1 < nk) {
            produce_r((t + 1) & 1, (t + 1) << 5);
            load_B((t + 1) & 1, (t + 1) << 5);
            CP_COMMIT(); CP_WAIT_1();
        } else {
            CP_WAIT_0();
        }
        __syncthreads();

        const uint32_t s = sb + (t & 1) * STAGE_BIG;
        #pragma unroll
        for (int k16 = 0; k16 < 2; k16++) {
            const uint32_t kb = (uint32_t)(k16 * 32);
            uint32_t ah[4][4], al[4][4], bh[4][4], bl[4][4];
            #pragma unroll
            for (int mt = 0; mt < 4; mt++) ldsm4(ah[mt], s + aoff[mt] + kb);
            #pragma unroll
            for (int n2 = 0; n2 < 4; n2++) ldsm4(bh[n2], s + OFFB_BH + boff[n2] + kb);
            #pragma unroll
            for (int mt = 0; mt < 4; mt++)
                #pragma unroll
                for (int nt = 0; nt < 8; nt++) {
                    const uint32_t* b = bh[nt >> 1];
                    mma16816(acc[mt][nt], ah[mt][0], ah[mt][1], ah[mt][2], ah[mt][3],
                             (nt & 1) ? b[1] : b[0], (nt & 1) ? b[3] : b[2]);
                }
            #pragma unroll
            for (int n2 = 0; n2 < 4; n2++) ldsm4(bl[n2], s + OFFB_BL + boff[n2] + kb);
            #pragma unroll
            for (int mt = 0; mt < 4; mt++)
                #pragma unroll
                for (int nt = 0; nt < 8; nt++) {
                    const uint32_t* b = bl[nt >> 1];
                    mma16816(acc[mt][nt], ah[mt][0], ah[mt][1], ah[mt][2], ah[mt][3],
                             (nt & 1) ? b[1] : b[0], (nt & 1) ? b[3] : b[2]);
                }
            #pragma unroll
            for (int mt = 0; mt < 4; mt++) ldsm4(al[mt], s + OFFB_AL + aoff[mt] + kb);
            #pragma unroll
            for (int mt = 0; mt < 4; mt++)
                #pragma unroll
                for (int nt = 0; nt < 8; nt++) {
                    const uint32_t* b = bh[nt >> 1];
                    mma16816(acc[mt][nt], al[mt][0], al[mt][1], al[mt][2], al[mt][3],
                             (nt & 1) ? b[1] : b[0], (nt & 1) ? b[3] : b[2]);
                }
        }
        __syncthreads();
    }

    const int group = lane >> 2, tig = lane & 3;
    #pragma unroll
    for (int mt = 0; mt < 4; mt++) {
        #pragma unroll
        for (int nt = 0; nt < 8; nt++) {
            int row = by * 256 + warp_m * 64 + mt * 16 + group;
            int col = bz * 128 + warp_n * 64 + nt * 8 + tig * 2;
            long long o0 = (long long)row * 2048 + col;
            long long o1 = o0 + 8LL * 2048;
            uint32_t lo0, lo1;
            uint32_t hi0 = pack_split_hi(acc[mt][nt][0], acc[mt][nt][1], lo0);
            uint32_t hi1 = pack_split_hi(acc[mt][nt][2], acc[mt][nt][3], lo1);
            *(uint32_t*)(Ch + o0) = hi0;
            *(uint32_t*)(Cl + o0) = lo0;
            *(uint32_t*)(Ch + o1) = hi1;
            *(uint32_t*)(Cl + o1) = lo1;
        }
    }
}

// ------------------------- launch ------------------------------------------
extern "C" void kernel_launch(void* const* d_in, const int* in_sizes, int n_in,
                              void* d_out, int out_size)
{
    (void)in_sizes; (void)n_in; (void)out_size;
    const float* dk   = (const float*)d_in[0];
    const float* dq   = (const float*)d_in[1];
    const float* dWk  = (const float*)d_in[2];
    const float* dWv  = (const float*)d_in[3];
    const float* dWo  = (const float*)d_in[4];
    const float* dwmu = (const float*)d_in[5];
    const float* dwsg = (const float*)d_in[6];
    float* dout = (float*)d_out;

    compute_G2_host();

    bf16 *pWh, *pWl, *pkh, *pkl, *pqh, *pql, *pWoh, *pWol, *pG2h, *pG2l;
    bf16 *pKVth, *pKVtl, *pkeysh, *pkeysl, *pvalTh, *pvalTl;
    bf16 *pctxh, *pctxl;
    float *ppart, *pparams;
    cudaGetSymbolAddress((void**)&pWh,   g_Wh);   cudaGetSymbolAddress((void**)&pWl,   g_Wl);
    cudaGetSymbolAddress((void**)&pkh,   g_kh);   cudaGetSymbolAddress((void**)&pkl,   g_kl);
    cudaGetSymbolAddress((void**)&pqh,   g_qh);   cudaGetSymbolAddress((void**)&pql,   g_ql);
    cudaGetSymbolAddress((void**)&pWoh,  g_Woh);  cudaGetSymbolAddress((void**)&pWol,  g_Wol);
    cudaGetSymbolAddress((void**)&pG2h,  g_G2h);  cudaGetSymbolAddress((void**)&pG2l,  g_G2l);
    cudaGetSymbolAddress((void**)&pKVth, g_KVth); cudaGetSymbolAddress((void**)&pKVtl, g_KVtl);
    cudaGetSymbolAddress((void**)&pkeysh,g_keysh);cudaGetSymbolAddress((void**)&pkeysl,g_keysl);
    cudaGetSymbolAddress((void**)&pvalTh,g_valTh);cudaGetSymbolAddress((void**)&pvalTl,g_valTl);
    cudaGetSymbolAddress((void**)&pctxh, g_ctxh); cudaGetSymbolAddress((void**)&pctxl, g_ctxl);
    cudaGetSymbolAddress((void**)&ppart, g_part); cudaGetSymbolAddress((void**)&pparams, g_params);

    cudaFuncSetAttribute(mma_gemm1,       cudaFuncAttributeMaxDynamicSharedMemorySize, SMEM_BYTES);
    cudaFuncSetAttribute(mma_big<0>,      cudaFuncAttributeMaxDynamicSharedMemorySize, SMEM_BIG);
    cudaFuncSetAttribute(mma_big<2>,      cudaFuncAttributeMaxDynamicSharedMemorySize, SMEM_BIG);
    cudaFuncSetAttribute(gemm2_fused_big, cudaFuncAttributeMaxDynamicSharedMemorySize, SMEM_BIG);
    cudaFuncSetAttribute(gemm_r_big,      cudaFuncAttributeMaxDynamicSharedMemorySize, SMEM_BIG);

    // setup (launch idx 0-4); idx 5 = first GEMM (ncu capture target)
    {
        int n4 = 2048 * 2048 / 4;
        split_kernel<<<(n4 + 255) / 256, 256>>>((const float4*)dWk, (uint2*)pWh, (uint2*)pWl, n4);
        split_kernel<<<(n4 + 255) / 256, 256>>>((const float4*)dWv,
                                                (uint2*)(pWh + 2048 * 2048), (uint2*)(pWl + 2048 * 2048), n4);
        int nk4 = 512 * 2048 / 4;
        split_kernel<<<(nk4 + 255) / 256, 256>>>((const float4*)dk, (uint2*)pkh, (uint2*)pkl, nk4);
        int n16 = 1024 * 512 * 2 / 16;
        copy_g2_kernel<<<(n16 + 255) / 256, 256>>>((const uint4*)hG2h, (const uint4*)hG2l,
                                                   (uint4*)pG2h, (uint4*)pG2l, n16);
        int nq4 = 16 * 2048 * 128 / 4;
        split_kernel<<<(nq4 + 255) / 256, 256>>>((const float4*)dq, (uint2*)pqh, (uint2*)pql, nq4);
    }

    // 1: KVt[z*2048+j][l] = W[z][j]·k[l]   (old kernel; N=512 too small for big tiles)
    {
        dim3 g(4, 16, 2);
        mma_gemm1<<<g, NT, SMEM_BYTES>>>(pWh, pWl, 2048, 2048LL * 2048,
                                         pkh, pkl, 2048, 0,
                                         pKVth, pKVtl, 512, 2048LL * 512,
                                         2048);
    }
    // Wo split (only needed before GEMM6)
    {
        int n4 = 2048 * 2048 / 4;
        split_kernel<<<(n4 + 255) / 256, 256>>>((const float4*)dWo, (uint2*)pWoh, (uint2*)pWol, n4);
    }
    // 2: fused keys + valT (128 big CTAs = one full wave)
    gemm2_fused_big<<<128, 256, SMEM_BIG>>>(pG2h, pG2l, pKVth, pKVtl,
                                            pkeysh, pkeysl, pvalTh, pvalTl);
    // 3: scores reduced in-register -> per-row partials (big tiles)
    {
        dim3 g(8, 8, 16);
        mma_big<2><<<g, 256, SMEM_BIG>>>(pqh, pql, 128, 2048LL * 128,
                                         pkeysh, pkeysl, 2048, 128,
                                         nullptr, nullptr, nullptr, 0, 0,
                                         128, 0.08838834764831845f, dwmu, dwsg, ppart);
    }
    // 4: fold partials -> row params
    reduce_params<<<128, 256>>>(ppart, pparams);

    // 5: ctx = r · valT^T, r staged through smem (big tiles)
    {
        dim3 g(1, 8, 16);
        gemm_r_big<<<g, 256, SMEM_BIG>>>(pvalTh, pvalTl, pparams, pctxh, pctxl);
    }
    // 6: out[q][o] = ctx[q]·Wo[o] (big tiles, 128 CTAs = one full wave)
    {
        dim3 g(16, 8, 1);
        mma_big<0><<<g, 256, SMEM_BIG>>>(pctxh, pctxl, 2048, 0,
                                         pWoh, pWol, 2048, 0,
                                         dout, nullptr, nullptr, 2048, 0,
                                         2048, 1.0f, nullptr, nullptr, nullptr);
    }
}